// round 5
// baseline (speedup 1.0000x reference)
#include <cuda_runtime.h>
#include <cuda_bf16.h>
#include <math.h>
#include <stdint.h>

#define BATCH 2048
#define HDIM  4096
#define NHEAD 4
#define HSZ   1024

#define BM 128
#define BN 128
#define BK 64              // bf16 elems per K-chunk (128B data rows)
#define NCHUNK 32          // 2 passes * (1024/64)
#define NSTAGE 3
#define NTHR 512

#define TSTRIDE 144        // 128B data + 16B pad; conflict-free for ldmatrix
#define TILE_B  (128 * TSTRIDE)          // 18432
#define STAGE_B (4 * TILE_B)             // Ah, Al, Bh, Bl = 73728
#define SMEM_B  (NSTAGE * STAGE_B)       // 221184

typedef __nv_bfloat16 bf16;

// ---------------- scratch (device globals; no runtime allocation) ----------
__device__ __align__(16) bf16 g_xn_hi  [(size_t)BATCH * HDIM];
__device__ __align__(16) bf16 g_xn_lo  [(size_t)BATCH * HDIM];
__device__ __align__(16) bf16 g_xact_hi[(size_t)BATCH * HDIM];
__device__ __align__(16) bf16 g_xact_lo[(size_t)BATCH * HDIM];
__device__ __align__(16) bf16 g_rec_hi [(size_t)BATCH * HDIM];
__device__ __align__(16) bf16 g_rec_lo [(size_t)BATCH * HDIM];
__device__ __align__(16) bf16 g_w_hi   [8ull * NHEAD * HSZ * HSZ];
__device__ __align__(16) bf16 g_w_lo   [8ull * NHEAD * HSZ * HSZ];
__device__ __align__(16) float g_gates [4ull * BATCH * HDIM];

// ---------------- helpers ---------------------------------------------------
__device__ __forceinline__ float warpSum(float v) {
#pragma unroll
    for (int o = 16; o > 0; o >>= 1) v += __shfl_down_sync(0xffffffffu, v, o);
    return v;
}

__device__ __forceinline__ uint32_t smem_u32(const void* p) {
    uint32_t a;
    asm("{ .reg .u64 t; cvta.to.shared.u64 t, %1; cvt.u32.u64 %0, t; }"
        : "=r"(a) : "l"(p));
    return a;
}

__device__ __forceinline__ void cp16(uint32_t saddr, const void* gaddr) {
    asm volatile("cp.async.cg.shared.global [%0], [%1], 16;"
                 :: "r"(saddr), "l"(gaddr));
}

__device__ __forceinline__ void ldsm4(uint32_t* r, uint32_t a) {
    asm volatile("ldmatrix.sync.aligned.m8n8.x4.shared.b16 {%0,%1,%2,%3}, [%4];"
                 : "=r"(r[0]), "=r"(r[1]), "=r"(r[2]), "=r"(r[3]) : "r"(a));
}

__device__ __forceinline__ void mma_bf16(float* c, const uint32_t* a,
                                         uint32_t b0, uint32_t b1) {
    asm volatile(
        "mma.sync.aligned.m16n8k16.row.col.f32.bf16.bf16.f32 "
        "{%0,%1,%2,%3}, {%4,%5,%6,%7}, {%8,%9}, {%0,%1,%2,%3};"
        : "+f"(c[0]), "+f"(c[1]), "+f"(c[2]), "+f"(c[3])
        : "r"(a[0]), "r"(a[1]), "r"(a[2]), "r"(a[3]), "r"(b0), "r"(b1));
}

__device__ __forceinline__ void split_bf16(float x, bf16& h, bf16& l) {
    h = __float2bfloat16(x);
    l = __float2bfloat16(x - __bfloat162float(h));
}

// ---------------- Kernel A: layernorm + conv + silu + hi/lo emit -----------
__global__ __launch_bounds__(256) void ln_conv_kernel(
    const float* __restrict__ x, const float* __restrict__ cs,
    const float* __restrict__ ln_w, const float* __restrict__ conv_w,
    const float* __restrict__ conv_b, float* __restrict__ out_ncs)
{
    const int b   = blockIdx.x;
    const int tid = threadIdx.x;
    const float* xr = x + (size_t)b * HDIM;

    float4 xv[4];
    float s = 0.f, sq = 0.f;
#pragma unroll
    for (int i = 0; i < 4; i++) {
        xv[i] = *(const float4*)(xr + (size_t)(tid + i * 256) * 4);
        s  += xv[i].x + xv[i].y + xv[i].z + xv[i].w;
        sq += xv[i].x * xv[i].x + xv[i].y * xv[i].y + xv[i].z * xv[i].z + xv[i].w * xv[i].w;
    }
    __shared__ float rs[8], rq[8];
    float ws = warpSum(s), wq = warpSum(sq);
    if ((tid & 31) == 0) { rs[tid >> 5] = ws; rq[tid >> 5] = wq; }
    __syncthreads();
    float ts = 0.f, tq = 0.f;
#pragma unroll
    for (int i = 0; i < 8; i++) { ts += rs[i]; tq += rq[i]; }
    const float mean = ts * (1.f / HDIM);
    const float var  = tq * (1.f / HDIM) - mean * mean;
    const float rstd = rsqrtf(var + 1e-5f);

    const float* csb = cs      + (size_t)b * 3 * HDIM;
    float*       ncs = out_ncs + (size_t)b * 3 * HDIM;

#pragma unroll
    for (int i = 0; i < 4; i++) {
        const int c = (tid + i * 256) * 4;
        float4 lw = *(const float4*)(ln_w + c);
        float4 xn;
        xn.x = (xv[i].x - mean) * rstd * lw.x;
        xn.y = (xv[i].y - mean) * rstd * lw.y;
        xn.z = (xv[i].z - mean) * rstd * lw.z;
        xn.w = (xv[i].w - mean) * rstd * lw.w;

        float4 c0 = *(const float4*)(csb + c);
        float4 c1 = *(const float4*)(csb + HDIM + c);
        float4 c2 = *(const float4*)(csb + 2 * HDIM + c);
        float4 cb = *(const float4*)(conv_b + c);
        float4 w0 = *(const float4*)(conv_w + (size_t)(c + 0) * 4);
        float4 w1 = *(const float4*)(conv_w + (size_t)(c + 1) * 4);
        float4 w2 = *(const float4*)(conv_w + (size_t)(c + 2) * 4);
        float4 w3 = *(const float4*)(conv_w + (size_t)(c + 3) * 4);

        float4 xc;
        xc.x = c0.x * w0.x + c1.x * w0.y + c2.x * w0.z + xn.x * w0.w + cb.x;
        xc.y = c0.y * w1.x + c1.y * w1.y + c2.y * w1.z + xn.y * w1.w + cb.y;
        xc.z = c0.z * w2.x + c1.z * w2.y + c2.z * w2.z + xn.z * w2.w + cb.z;
        xc.w = c0.w * w3.x + c1.w * w3.y + c2.w * w3.z + xn.w * w3.w + cb.w;

        float4 xa;
        xa.x = xc.x / (1.f + expf(-xc.x));
        xa.y = xc.y / (1.f + expf(-xc.y));
        xa.z = xc.z / (1.f + expf(-xc.z));
        xa.w = xc.w / (1.f + expf(-xc.w));

        union { bf16 bb[4]; uint2 u; } nh, nl, ah, al;
        split_bf16(xn.x, nh.bb[0], nl.bb[0]); split_bf16(xn.y, nh.bb[1], nl.bb[1]);
        split_bf16(xn.z, nh.bb[2], nl.bb[2]); split_bf16(xn.w, nh.bb[3], nl.bb[3]);
        split_bf16(xa.x, ah.bb[0], al.bb[0]); split_bf16(xa.y, ah.bb[1], al.bb[1]);
        split_bf16(xa.z, ah.bb[2], al.bb[2]); split_bf16(xa.w, ah.bb[3], al.bb[3]);

        const size_t off = (size_t)b * HDIM + c;
        *(uint2*)(g_xn_hi   + off) = nh.u;
        *(uint2*)(g_xn_lo   + off) = nl.u;
        *(uint2*)(g_xact_hi + off) = ah.u;
        *(uint2*)(g_xact_lo + off) = al.u;

        *(float4*)(ncs + c)            = c1;
        *(float4*)(ncs + HDIM + c)     = c2;
        *(float4*)(ncs + 2 * HDIM + c) = xn;
    }
}

// ---------------- conversion kernels ----------------------------------------
__global__ __launch_bounds__(256) void convert_w_kernel(
    const float* __restrict__ w0, const float* __restrict__ w1,
    const float* __restrict__ w2, const float* __restrict__ w3,
    const float* __restrict__ w4, const float* __restrict__ w5,
    const float* __restrict__ w6, const float* __restrict__ w7)
{
    const float* srcs[8] = { w0, w1, w2, w3, w4, w5, w6, w7 };
    const float* s = srcs[blockIdx.y];
    const size_t base4 = (size_t)blockIdx.y * (NHEAD * HSZ * (HSZ / 4));
    const int i = blockIdx.x * 256 + threadIdx.x;
    float4 v = ((const float4*)s)[i];
    union { bf16 bb[4]; uint2 u; } h, l;
    split_bf16(v.x, h.bb[0], l.bb[0]); split_bf16(v.y, h.bb[1], l.bb[1]);
    split_bf16(v.z, h.bb[2], l.bb[2]); split_bf16(v.w, h.bb[3], l.bb[3]);
    ((uint2*)g_w_hi)[base4 + i] = h.u;
    ((uint2*)g_w_lo)[base4 + i] = l.u;
}

__global__ __launch_bounds__(256) void convert_rec_kernel(const float* __restrict__ src)
{
    const int i = blockIdx.x * 256 + threadIdx.x;
    float4 v = ((const float4*)src)[i];
    union { bf16 bb[4]; uint2 u; } h, l;
    split_bf16(v.x, h.bb[0], l.bb[0]); split_bf16(v.y, h.bb[1], l.bb[1]);
    split_bf16(v.z, h.bb[2], l.bb[2]); split_bf16(v.w, h.bb[3], l.bb[3]);
    ((uint2*)g_rec_hi)[i] = h.u;
    ((uint2*)g_rec_lo)[i] = l.u;
}

// ---------------- Kernel B: HMMA bf16-split GEMM (16 warps, 3-stage) -------
__global__ __launch_bounds__(NTHR, 1) void gemm_kernel(
    const float* __restrict__ bi, const float* __restrict__ bf_,
    const float* __restrict__ bz, const float* __restrict__ bo)
{
    extern __shared__ __align__(1024) char smem[];
    const uint32_t sbase = smem_u32(smem);
    const int tid  = threadIdx.x;
    const int wid  = tid >> 5;
    const int lane = tid & 31;

    const int g  = blockIdx.z >> 2;
    const int nh = blockIdx.z & 3;
    const int m0 = blockIdx.y * BM;
    const int n0 = blockIdx.x * BN;

    const bf16* aHi0 = (g < 2 ? g_xact_hi : g_xn_hi);
    const bf16* aLo0 = (g < 2 ? g_xact_lo : g_xn_lo);
    const size_t wb0 = ((size_t)g)       * NHEAD * HSZ * HSZ + (size_t)nh * HSZ * HSZ;
    const size_t wb1 = ((size_t)(g + 4)) * NHEAD * HSZ * HSZ + (size_t)nh * HSZ * HSZ;

    // loader: 8 cp16 per thread per chunk
    auto load_chunk = [&](int c) {
        const int pass = c >> 4;
        const int kt   = (c & 15) * BK;
        const uint32_t st = sbase + (uint32_t)(c % NSTAGE) * STAGE_B;
        const bf16* aH = (pass ? g_rec_hi : aHi0);
        const bf16* aL = (pass ? g_rec_lo : aLo0);
        const bf16* wH = g_w_hi + (pass ? wb1 : wb0);
        const bf16* wL = g_w_lo + (pass ? wb1 : wb0);
#pragma unroll
        for (int t = 0; t < 2; t++) {
            const int idx = tid + t * NTHR;         // 0..1023
            const int row = idx >> 3;
            const int sec = idx & 7;
            const uint32_t sdst = st + (uint32_t)row * TSTRIDE + sec * 16;
            const size_t aoff = (size_t)(m0 + row) * HDIM + (size_t)nh * HSZ + kt + sec * 8;
            const size_t boff = (size_t)(n0 + row) * HSZ + kt + sec * 8;
            cp16(sdst,              aH + aoff);
            cp16(sdst + TILE_B,     aL + aoff);
            cp16(sdst + 2 * TILE_B, wH + boff);
            cp16(sdst + 3 * TILE_B, wL + boff);
        }
    };

    // warp tiling: 4 warps along M (32 rows), 4 along N (32 cols)
    const int wm = wid & 3;
    const int wn = wid >> 2;

    const uint32_t aRowOff = (uint32_t)(wm * 32 + (lane & 15)) * TSTRIDE + ((lane >> 4) << 4);
    const uint32_t bRowOff = (uint32_t)(wn * 32 + (lane & 7) + ((lane >> 4) << 3)) * TSTRIDE
                             + (((lane >> 3) & 1) << 4);

    float acc[2][4][4];
#pragma unroll
    for (int mi = 0; mi < 2; mi++)
#pragma unroll
        for (int j = 0; j < 4; j++)
#pragma unroll
            for (int q = 0; q < 4; q++) acc[mi][j][q] = 0.f;

    load_chunk(0);
    asm volatile("cp.async.commit_group;");
    load_chunk(1);
    asm volatile("cp.async.commit_group;");

#pragma unroll 1
    for (int c = 0; c < NCHUNK; c++) {
        asm volatile("cp.async.wait_group 1;");
        __syncthreads();                     // chunk c visible; compute on c-1 done

        if (c + 2 < NCHUNK) load_chunk(c + 2);
        asm volatile("cp.async.commit_group;");

        const uint32_t st = sbase + (uint32_t)(c % NSTAGE) * STAGE_B;
#pragma unroll
        for (int kk = 0; kk < 4; kk++) {
            uint32_t ah[2][4], al[2][4];
            const uint32_t ka = st + aRowOff + kk * 32;
            ldsm4(ah[0], ka);
            ldsm4(ah[1], ka + 16 * TSTRIDE);
            ldsm4(al[0], ka + TILE_B);
            ldsm4(al[1], ka + TILE_B + 16 * TSTRIDE);

            uint32_t Bh[2][4], Bl[2][4];
#pragma unroll
            for (int jj = 0; jj < 2; jj++) {
                const uint32_t kb = st + 2 * TILE_B + bRowOff + jj * 16 * TSTRIDE + kk * 32;
                ldsm4(Bh[jj], kb);
                ldsm4(Bl[jj], kb + TILE_B);
            }
            // term hi*hi
#pragma unroll
            for (int jj = 0; jj < 2; jj++)
#pragma unroll
                for (int mi = 0; mi < 2; mi++) {
                    mma_bf16(acc[mi][2 * jj],     ah[mi], Bh[jj][0], Bh[jj][1]);
                    mma_bf16(acc[mi][2 * jj + 1], ah[mi], Bh[jj][2], Bh[jj][3]);
                }
            // term hi*lo
#pragma unroll
            for (int jj = 0; jj < 2; jj++)
#pragma unroll
                for (int mi = 0; mi < 2; mi++) {
                    mma_bf16(acc[mi][2 * jj],     ah[mi], Bl[jj][0], Bl[jj][1]);
                    mma_bf16(acc[mi][2 * jj + 1], ah[mi], Bl[jj][2], Bl[jj][3]);
                }
            // term lo*hi
#pragma unroll
            for (int jj = 0; jj < 2; jj++)
#pragma unroll
                for (int mi = 0; mi < 2; mi++) {
                    mma_bf16(acc[mi][2 * jj],     al[mi], Bh[jj][0], Bh[jj][1]);
                    mma_bf16(acc[mi][2 * jj + 1], al[mi], Bh[jj][2], Bh[jj][3]);
                }
        }
    }

    // epilogue: add bias, write gates
    const float* bias = (g == 0) ? bi : (g == 1) ? bf_ : (g == 2) ? bz : bo;
    float* gbase = g_gates + (size_t)g * BATCH * HDIM;

#pragma unroll
    for (int mi = 0; mi < 2; mi++) {
        const int row0 = m0 + wm * 32 + mi * 16 + (lane >> 2);
#pragma unroll
        for (int j = 0; j < 4; j++) {
            const int col = n0 + wn * 32 + j * 8 + (lane & 3) * 2;
            const int h   = nh * HSZ + col;
            const float b0 = bias[h], b1 = bias[h + 1];
            float* p0 = gbase + (size_t)row0 * HDIM + h;
            float* p1 = p0 + 8 * HDIM;
            *(float2*)p0 = make_float2(acc[mi][j][0] + b0, acc[mi][j][1] + b1);
            *(float2*)p1 = make_float2(acc[mi][j][2] + b0, acc[mi][j][3] + b1);
        }
    }
}

// ---------------- Kernel C: gate math + group norm + outputs ---------------
__global__ __launch_bounds__(256) void gate_kernel(
    const float* __restrict__ x,      const float* __restrict__ cell,
    const float* __restrict__ normst, const float* __restrict__ maxst,
    const float* __restrict__ gn_w,   const float* __restrict__ gn_b,
    float* __restrict__ dout)
{
    const int blk = blockIdx.x;
    const int b = blk >> 2, n = blk & 3;
    const int tid = threadIdx.x;
    const size_t BH = (size_t)BATCH * HDIM;
    const size_t base = (size_t)b * HDIM + n * HSZ;
    const int c = tid * 4;

    float4 t;
    float iv[4], fv[4], zv[4], ov[4], cv[4], nv[4], mv[4];
    t = *(const float4*)(g_gates + 0 * BH + base + c); iv[0]=t.x; iv[1]=t.y; iv[2]=t.z; iv[3]=t.w;
    t = *(const float4*)(g_gates + 1 * BH + base + c); fv[0]=t.x; fv[1]=t.y; fv[2]=t.z; fv[3]=t.w;
    t = *(const float4*)(g_gates + 2 * BH + base + c); zv[0]=t.x; zv[1]=t.y; zv[2]=t.z; zv[3]=t.w;
    t = *(const float4*)(g_gates + 3 * BH + base + c); ov[0]=t.x; ov[1]=t.y; ov[2]=t.z; ov[3]=t.w;
    t = *(const float4*)(cell   + base + c); cv[0]=t.x; cv[1]=t.y; cv[2]=t.z; cv[3]=t.w;
    t = *(const float4*)(normst + base + c); nv[0]=t.x; nv[1]=t.y; nv[2]=t.z; nv[3]=t.w;
    t = *(const float4*)(maxst  + base + c); mv[0]=t.x; mv[1]=t.y; mv[2]=t.z; mv[3]=t.w;

    float y[4], cn[4], nn[4], mn[4];
    float s = 0.f, sq = 0.f;
#pragma unroll
    for (int j = 0; j < 4; ++j) {
        float fj  = fv[j];
        float lsf = fminf(fj, 0.f) - log1pf(expf(-fabsf(fj)));
        float lfm = mv[j] + lsf;
        float ij  = iv[j];
        float mnew = fmaxf(ij, lfm);
        float ig = expf(ij  - mnew);
        float fg = expf(lfm - mnew);
        float cnew = fg * cv[j] + ig * tanhf(zv[j]);
        float nnew = fg * nv[j] + ig;
        float so   = 1.f / (1.f + expf(-ov[j]));
        float yj   = so * cnew / (nnew + 1e-6f);
        y[j] = yj; cn[j] = cnew; nn[j] = nnew; mn[j] = mnew;
        s += yj; sq += yj * yj;
    }

    __shared__ float rs[8], rq[8];
    float ws = warpSum(s), wq = warpSum(sq);
    if ((tid & 31) == 0) { rs[tid >> 5] = ws; rq[tid >> 5] = wq; }
    __syncthreads();
    float ts = 0.f, tq = 0.f;
#pragma unroll
    for (int i = 0; i < 8; i++) { ts += rs[i]; tq += rq[i]; }
    const float mean = ts * (1.f / HSZ);
    const float var  = tq * (1.f / HSZ) - mean * mean;
    const float rstd = rsqrtf(var + 1e-5f);

    const int h = n * HSZ + c;
    float4 gw = *(const float4*)(gn_w + h);
    float4 gb = *(const float4*)(gn_b + h);
    float4 xs = *(const float4*)(x + base + c);
    const float gwv[4] = { gw.x, gw.y, gw.z, gw.w };
    const float gbv[4] = { gb.x, gb.y, gb.z, gb.w };
    const float xv4[4] = { xs.x, xs.y, xs.z, xs.w };

    float ot[4];
#pragma unroll
    for (int j = 0; j < 4; ++j)
        ot[j] = (y[j] - mean) * rstd * gwv[j] + gbv[j] + xv4[j];

    *(float4*)(dout + 0 * BH + base + c) = make_float4(ot[0], ot[1], ot[2], ot[3]);
    *(float4*)(dout + 4 * BH + base + c) = make_float4(y[0],  y[1],  y[2],  y[3]);
    *(float4*)(dout + 5 * BH + base + c) = make_float4(cn[0], cn[1], cn[2], cn[3]);
    *(float4*)(dout + 6 * BH + base + c) = make_float4(nn[0], nn[1], nn[2], nn[3]);
    *(float4*)(dout + 7 * BH + base + c) = make_float4(mn[0], mn[1], mn[2], mn[3]);
}

// ---------------- launch -----------------------------------------------------
extern "C" void kernel_launch(void* const* d_in, const int* in_sizes, int n_in,
                              void* d_out, int out_size)
{
    const float* x      = (const float*)d_in[0];
    const float* cs     = (const float*)d_in[1];
    const float* rec    = (const float*)d_in[2];
    const float* cell   = (const float*)d_in[3];
    const float* normst = (const float*)d_in[4];
    const float* maxst  = (const float*)d_in[5];
    const float* ln_w   = (const float*)d_in[6];
    const float* conv_w = (const float*)d_in[7];
    const float* conv_b = (const float*)d_in[8];
    const float* wi_in  = (const float*)d_in[9];
    const float* wf_in  = (const float*)d_in[10];
    const float* wz_in  = (const float*)d_in[11];
    const float* wo_in  = (const float*)d_in[12];
    const float* wi_st  = (const float*)d_in[13];
    const float* wf_st  = (const float*)d_in[14];
    const float* wz_st  = (const float*)d_in[15];
    const float* wo_st  = (const float*)d_in[16];
    const float* bi     = (const float*)d_in[17];
    const float* bf_    = (const float*)d_in[18];
    const float* bz     = (const float*)d_in[19];
    const float* bo     = (const float*)d_in[20];
    const float* gn_w   = (const float*)d_in[21];
    const float* gn_b   = (const float*)d_in[22];
    float* out = (float*)d_out;

    static int smem_set = 0;
    if (!smem_set) {
        cudaFuncSetAttribute(gemm_kernel, cudaFuncAttributeMaxDynamicSharedMemorySize,
                             SMEM_B);
        smem_set = 1;
    }

    ln_conv_kernel<<<BATCH, 256>>>(x, cs, ln_w, conv_w, conv_b,
                                   out + (size_t)BATCH * HDIM);

    convert_w_kernel<<<dim3(4096, 8), 256>>>(wi_in, wf_in, wz_in, wo_in,
                                             wi_st, wf_st, wz_st, wo_st);
    convert_rec_kernel<<<8192, 256>>>(rec);

    dim3 grid(HSZ / BN, BATCH / BM, 16);
    gemm_kernel<<<grid, NTHR, SMEM_B>>>(bi, bf_, bz, bo);

    gate_kernel<<<BATCH * NHEAD, 256>>>(x, cell, normst, maxst, gn_w, gn_b, out);
}

// round 6
// speedup vs baseline: 1.0143x; 1.0143x over previous
#include <cuda_runtime.h>
#include <cuda_bf16.h>
#include <math.h>
#include <stdint.h>

#define BATCH 2048
#define HDIM  4096
#define NHEAD 4
#define HSZ   1024

#define BM 128
#define BN 128
#define BK 64              // bf16 elems per K-chunk (128B data rows)
#define NCHUNK 32          // 2 passes * (1024/64)
#define NSTAGE 3

#define TSTRIDE 144        // 128B data + 16B pad; conflict-free for ldmatrix
#define TILE_B  (128 * TSTRIDE)          // 18432
#define STAGE_B (4 * TILE_B)             // Ah, Al, Bh, Bl = 73728
#define SMEM_B  (NSTAGE * STAGE_B)       // 221184

typedef __nv_bfloat16 bf16;

// ---------------- scratch (device globals; no runtime allocation) ----------
__device__ __align__(16) bf16 g_xn_hi  [(size_t)BATCH * HDIM];
__device__ __align__(16) bf16 g_xn_lo  [(size_t)BATCH * HDIM];
__device__ __align__(16) bf16 g_xact_hi[(size_t)BATCH * HDIM];
__device__ __align__(16) bf16 g_xact_lo[(size_t)BATCH * HDIM];
__device__ __align__(16) bf16 g_rec_hi [(size_t)BATCH * HDIM];
__device__ __align__(16) bf16 g_rec_lo [(size_t)BATCH * HDIM];
__device__ __align__(16) bf16 g_w_hi   [8ull * NHEAD * HSZ * HSZ];
__device__ __align__(16) bf16 g_w_lo   [8ull * NHEAD * HSZ * HSZ];
__device__ __align__(16) float g_gates [4ull * BATCH * HDIM];

// ---------------- helpers ---------------------------------------------------
__device__ __forceinline__ float warpSum(float v) {
#pragma unroll
    for (int o = 16; o > 0; o >>= 1) v += __shfl_down_sync(0xffffffffu, v, o);
    return v;
}

__device__ __forceinline__ uint32_t smem_u32(const void* p) {
    uint32_t a;
    asm("{ .reg .u64 t; cvta.to.shared.u64 t, %1; cvt.u32.u64 %0, t; }"
        : "=r"(a) : "l"(p));
    return a;
}

__device__ __forceinline__ void cp16(uint32_t saddr, const void* gaddr) {
    asm volatile("cp.async.cg.shared.global [%0], [%1], 16;"
                 :: "r"(saddr), "l"(gaddr));
}

__device__ __forceinline__ void ldsm4(uint32_t* r, uint32_t a) {
    asm volatile("ldmatrix.sync.aligned.m8n8.x4.shared.b16 {%0,%1,%2,%3}, [%4];"
                 : "=r"(r[0]), "=r"(r[1]), "=r"(r[2]), "=r"(r[3]) : "r"(a));
}

__device__ __forceinline__ void mma_bf16(float* c, const uint32_t* a,
                                         uint32_t b0, uint32_t b1) {
    asm volatile(
        "mma.sync.aligned.m16n8k16.row.col.f32.bf16.bf16.f32 "
        "{%0,%1,%2,%3}, {%4,%5,%6,%7}, {%8,%9}, {%0,%1,%2,%3};"
        : "+f"(c[0]), "+f"(c[1]), "+f"(c[2]), "+f"(c[3])
        : "r"(a[0]), "r"(a[1]), "r"(a[2]), "r"(a[3]), "r"(b0), "r"(b1));
}

__device__ __forceinline__ void split_bf16(float x, bf16& h, bf16& l) {
    h = __float2bfloat16(x);
    l = __float2bfloat16(x - __bfloat162float(h));
}

// ---------------- Kernel A: layernorm + conv + silu + hi/lo emit -----------
__global__ __launch_bounds__(256) void ln_conv_kernel(
    const float* __restrict__ x, const float* __restrict__ cs,
    const float* __restrict__ ln_w, const float* __restrict__ conv_w,
    const float* __restrict__ conv_b, float* __restrict__ out_ncs)
{
    const int b   = blockIdx.x;
    const int tid = threadIdx.x;
    const float* xr = x + (size_t)b * HDIM;

    float4 xv[4];
    float s = 0.f, sq = 0.f;
#pragma unroll
    for (int i = 0; i < 4; i++) {
        xv[i] = *(const float4*)(xr + (size_t)(tid + i * 256) * 4);
        s  += xv[i].x + xv[i].y + xv[i].z + xv[i].w;
        sq += xv[i].x * xv[i].x + xv[i].y * xv[i].y + xv[i].z * xv[i].z + xv[i].w * xv[i].w;
    }
    __shared__ float rs[8], rq[8];
    float ws = warpSum(s), wq = warpSum(sq);
    if ((tid & 31) == 0) { rs[tid >> 5] = ws; rq[tid >> 5] = wq; }
    __syncthreads();
    float ts = 0.f, tq = 0.f;
#pragma unroll
    for (int i = 0; i < 8; i++) { ts += rs[i]; tq += rq[i]; }
    const float mean = ts * (1.f / HDIM);
    const float var  = tq * (1.f / HDIM) - mean * mean;
    const float rstd = rsqrtf(var + 1e-5f);

    const float* csb = cs      + (size_t)b * 3 * HDIM;
    float*       ncs = out_ncs + (size_t)b * 3 * HDIM;

#pragma unroll
    for (int i = 0; i < 4; i++) {
        const int c = (tid + i * 256) * 4;
        float4 lw = *(const float4*)(ln_w + c);
        float4 xn;
        xn.x = (xv[i].x - mean) * rstd * lw.x;
        xn.y = (xv[i].y - mean) * rstd * lw.y;
        xn.z = (xv[i].z - mean) * rstd * lw.z;
        xn.w = (xv[i].w - mean) * rstd * lw.w;

        float4 c0 = *(const float4*)(csb + c);
        float4 c1 = *(const float4*)(csb + HDIM + c);
        float4 c2 = *(const float4*)(csb + 2 * HDIM + c);
        float4 cb = *(const float4*)(conv_b + c);
        float4 w0 = *(const float4*)(conv_w + (size_t)(c + 0) * 4);
        float4 w1 = *(const float4*)(conv_w + (size_t)(c + 1) * 4);
        float4 w2 = *(const float4*)(conv_w + (size_t)(c + 2) * 4);
        float4 w3 = *(const float4*)(conv_w + (size_t)(c + 3) * 4);

        float4 xc;
        xc.x = c0.x * w0.x + c1.x * w0.y + c2.x * w0.z + xn.x * w0.w + cb.x;
        xc.y = c0.y * w1.x + c1.y * w1.y + c2.y * w1.z + xn.y * w1.w + cb.y;
        xc.z = c0.z * w2.x + c1.z * w2.y + c2.z * w2.z + xn.z * w2.w + cb.z;
        xc.w = c0.w * w3.x + c1.w * w3.y + c2.w * w3.z + xn.w * w3.w + cb.w;

        float4 xa;
        xa.x = xc.x / (1.f + expf(-xc.x));
        xa.y = xc.y / (1.f + expf(-xc.y));
        xa.z = xc.z / (1.f + expf(-xc.z));
        xa.w = xc.w / (1.f + expf(-xc.w));

        union { bf16 bb[4]; uint2 u; } nh, nl, ah, al;
        split_bf16(xn.x, nh.bb[0], nl.bb[0]); split_bf16(xn.y, nh.bb[1], nl.bb[1]);
        split_bf16(xn.z, nh.bb[2], nl.bb[2]); split_bf16(xn.w, nh.bb[3], nl.bb[3]);
        split_bf16(xa.x, ah.bb[0], al.bb[0]); split_bf16(xa.y, ah.bb[1], al.bb[1]);
        split_bf16(xa.z, ah.bb[2], al.bb[2]); split_bf16(xa.w, ah.bb[3], al.bb[3]);

        const size_t off = (size_t)b * HDIM + c;
        *(uint2*)(g_xn_hi   + off) = nh.u;
        *(uint2*)(g_xn_lo   + off) = nl.u;
        *(uint2*)(g_xact_hi + off) = ah.u;
        *(uint2*)(g_xact_lo + off) = al.u;

        *(float4*)(ncs + c)            = c1;
        *(float4*)(ncs + HDIM + c)     = c2;
        *(float4*)(ncs + 2 * HDIM + c) = xn;
    }
}

// ---------------- conversion kernels ----------------------------------------
__global__ __launch_bounds__(256) void convert_w_kernel(
    const float* __restrict__ w0, const float* __restrict__ w1,
    const float* __restrict__ w2, const float* __restrict__ w3,
    const float* __restrict__ w4, const float* __restrict__ w5,
    const float* __restrict__ w6, const float* __restrict__ w7)
{
    const float* srcs[8] = { w0, w1, w2, w3, w4, w5, w6, w7 };
    const float* s = srcs[blockIdx.y];
    const size_t base4 = (size_t)blockIdx.y * (NHEAD * HSZ * (HSZ / 4));
    const int i = blockIdx.x * 256 + threadIdx.x;
    float4 v = ((const float4*)s)[i];
    union { bf16 bb[4]; uint2 u; } h, l;
    split_bf16(v.x, h.bb[0], l.bb[0]); split_bf16(v.y, h.bb[1], l.bb[1]);
    split_bf16(v.z, h.bb[2], l.bb[2]); split_bf16(v.w, h.bb[3], l.bb[3]);
    ((uint2*)g_w_hi)[base4 + i] = h.u;
    ((uint2*)g_w_lo)[base4 + i] = l.u;
}

__global__ __launch_bounds__(256) void convert_rec_kernel(const float* __restrict__ src)
{
    const int i = blockIdx.x * 256 + threadIdx.x;
    float4 v = ((const float4*)src)[i];
    union { bf16 bb[4]; uint2 u; } h, l;
    split_bf16(v.x, h.bb[0], l.bb[0]); split_bf16(v.y, h.bb[1], l.bb[1]);
    split_bf16(v.z, h.bb[2], l.bb[2]); split_bf16(v.w, h.bb[3], l.bb[3]);
    ((uint2*)g_rec_hi)[i] = h.u;
    ((uint2*)g_rec_lo)[i] = l.u;
}

// ---------------- Kernel B: HMMA bf16-split GEMM (frag double-buffer) ------
__global__ __launch_bounds__(256, 1) void gemm_kernel(
    const float* __restrict__ bi, const float* __restrict__ bf_,
    const float* __restrict__ bz, const float* __restrict__ bo)
{
    extern __shared__ __align__(1024) char smem[];
    const uint32_t sbase = smem_u32(smem);
    const int tid  = threadIdx.x;
    const int wid  = tid >> 5;
    const int lane = tid & 31;

    const int g  = blockIdx.z >> 2;
    const int nh = blockIdx.z & 3;
    const int m0 = blockIdx.y * BM;
    const int n0 = blockIdx.x * BN;

    const bf16* aHi0 = (g < 2 ? g_xact_hi : g_xn_hi);
    const bf16* aLo0 = (g < 2 ? g_xact_lo : g_xn_lo);
    const size_t wb0 = ((size_t)g)       * NHEAD * HSZ * HSZ + (size_t)nh * HSZ * HSZ;
    const size_t wb1 = ((size_t)(g + 4)) * NHEAD * HSZ * HSZ + (size_t)nh * HSZ * HSZ;

    // loader: 16 cp16 per thread per chunk
    auto load_chunk = [&](int c) {
        const int pass = c >> 4;
        const int kt   = (c & 15) * BK;
        const uint32_t st = sbase + (uint32_t)(c % NSTAGE) * STAGE_B;
        const bf16* aH = (pass ? g_rec_hi : aHi0);
        const bf16* aL = (pass ? g_rec_lo : aLo0);
        const bf16* wH = g_w_hi + (pass ? wb1 : wb0);
        const bf16* wL = g_w_lo + (pass ? wb1 : wb0);
#pragma unroll
        for (int t = 0; t < 4; t++) {
            const int idx = tid + t * 256;          // 0..1023
            const int row = idx >> 3;
            const int sec = idx & 7;
            const uint32_t sdst = st + (uint32_t)row * TSTRIDE + sec * 16;
            const size_t aoff = (size_t)(m0 + row) * HDIM + (size_t)nh * HSZ + kt + sec * 8;
            const size_t boff = (size_t)(n0 + row) * HSZ + kt + sec * 8;
            cp16(sdst,              aH + aoff);
            cp16(sdst + TILE_B,     aL + aoff);
            cp16(sdst + 2 * TILE_B, wH + boff);
            cp16(sdst + 3 * TILE_B, wL + boff);
        }
    };

    // warp tiling: 4 warps along M (32 rows), 2 along N (64 cols)
    const int wm = wid & 3;
    const int wn = wid >> 2;

    const uint32_t aRowOff = (uint32_t)(wm * 32 + (lane & 15)) * TSTRIDE + ((lane >> 4) << 4);
    const uint32_t bRowOff = (uint32_t)(wn * 64 + (lane & 7) + ((lane >> 4) << 3)) * TSTRIDE
                             + (((lane >> 3) & 1) << 4);

    float acc[2][8][4];
#pragma unroll
    for (int mi = 0; mi < 2; mi++)
#pragma unroll
        for (int j = 0; j < 8; j++)
#pragma unroll
            for (int q = 0; q < 4; q++) acc[mi][j][q] = 0.f;

    // fragment double buffers
    uint32_t ah[2][2][4], al[2][2][4], Bh[2][4][4], Bl[2][4][4];
    uint32_t stCur = sbase;   // stage base for current chunk

    auto load_frags = [&](int kk, int buf) {
        const uint32_t ka = stCur + aRowOff + kk * 32;
        ldsm4(ah[buf][0], ka);
        ldsm4(ah[buf][1], ka + 16 * TSTRIDE);
        ldsm4(al[buf][0], ka + TILE_B);
        ldsm4(al[buf][1], ka + TILE_B + 16 * TSTRIDE);
#pragma unroll
        for (int jj = 0; jj < 4; jj++) {
            const uint32_t kb = stCur + 2 * TILE_B + bRowOff + jj * 16 * TSTRIDE + kk * 32;
            ldsm4(Bh[buf][jj], kb);
            ldsm4(Bl[buf][jj], kb + TILE_B);
        }
    };

    load_chunk(0);
    asm volatile("cp.async.commit_group;");
    load_chunk(1);
    asm volatile("cp.async.commit_group;");

#pragma unroll 1
    for (int c = 0; c < NCHUNK; c++) {
        asm volatile("cp.async.wait_group 1;");
        __syncthreads();                     // chunk c visible; compute c-1 done

        if (c + 2 < NCHUNK) load_chunk(c + 2);
        asm volatile("cp.async.commit_group;");

        stCur = sbase + (uint32_t)(c % NSTAGE) * STAGE_B;
        load_frags(0, 0);

#pragma unroll
        for (int kk = 0; kk < 4; kk++) {
            const int buf = kk & 1;
            if (kk < 3) load_frags(kk + 1, buf ^ 1);

            // term hi*hi
#pragma unroll
            for (int jj = 0; jj < 4; jj++)
#pragma unroll
                for (int mi = 0; mi < 2; mi++) {
                    mma_bf16(acc[mi][2 * jj],     ah[buf][mi], Bh[buf][jj][0], Bh[buf][jj][1]);
                    mma_bf16(acc[mi][2 * jj + 1], ah[buf][mi], Bh[buf][jj][2], Bh[buf][jj][3]);
                }
            // term hi*lo
#pragma unroll
            for (int jj = 0; jj < 4; jj++)
#pragma unroll
                for (int mi = 0; mi < 2; mi++) {
                    mma_bf16(acc[mi][2 * jj],     ah[buf][mi], Bl[buf][jj][0], Bl[buf][jj][1]);
                    mma_bf16(acc[mi][2 * jj + 1], ah[buf][mi], Bl[buf][jj][2], Bl[buf][jj][3]);
                }
            // term lo*hi
#pragma unroll
            for (int jj = 0; jj < 4; jj++)
#pragma unroll
                for (int mi = 0; mi < 2; mi++) {
                    mma_bf16(acc[mi][2 * jj],     al[buf][mi], Bh[buf][jj][0], Bh[buf][jj][1]);
                    mma_bf16(acc[mi][2 * jj + 1], al[buf][mi], Bh[buf][jj][2], Bh[buf][jj][3]);
                }
        }
    }

    // epilogue: add bias, write gates
    const float* bias = (g == 0) ? bi : (g == 1) ? bf_ : (g == 2) ? bz : bo;
    float* gbase = g_gates + (size_t)g * BATCH * HDIM;

#pragma unroll
    for (int mi = 0; mi < 2; mi++) {
        const int row0 = m0 + wm * 32 + mi * 16 + (lane >> 2);
#pragma unroll
        for (int j = 0; j < 8; j++) {
            const int col = n0 + wn * 64 + j * 8 + (lane & 3) * 2;
            const int h   = nh * HSZ + col;
            const float b0 = bias[h], b1 = bias[h + 1];
            float* p0 = gbase + (size_t)row0 * HDIM + h;
            float* p1 = p0 + 8 * HDIM;
            *(float2*)p0 = make_float2(acc[mi][j][0] + b0, acc[mi][j][1] + b1);
            *(float2*)p1 = make_float2(acc[mi][j][2] + b0, acc[mi][j][3] + b1);
        }
    }
}

// ---------------- Kernel C: gate math + group norm + outputs ---------------
__global__ __launch_bounds__(256) void gate_kernel(
    const float* __restrict__ x,      const float* __restrict__ cell,
    const float* __restrict__ normst, const float* __restrict__ maxst,
    const float* __restrict__ gn_w,   const float* __restrict__ gn_b,
    float* __restrict__ dout)
{
    const int blk = blockIdx.x;
    const int b = blk >> 2, n = blk & 3;
    const int tid = threadIdx.x;
    const size_t BH = (size_t)BATCH * HDIM;
    const size_t base = (size_t)b * HDIM + n * HSZ;
    const int c = tid * 4;

    float4 t;
    float iv[4], fv[4], zv[4], ov[4], cv[4], nv[4], mv[4];
    t = *(const float4*)(g_gates + 0 * BH + base + c); iv[0]=t.x; iv[1]=t.y; iv[2]=t.z; iv[3]=t.w;
    t = *(const float4*)(g_gates + 1 * BH + base + c); fv[0]=t.x; fv[1]=t.y; fv[2]=t.z; fv[3]=t.w;
    t = *(const float4*)(g_gates + 2 * BH + base + c); zv[0]=t.x; zv[1]=t.y; zv[2]=t.z; zv[3]=t.w;
    t = *(const float4*)(g_gates + 3 * BH + base + c); ov[0]=t.x; ov[1]=t.y; ov[2]=t.z; ov[3]=t.w;
    t = *(const float4*)(cell   + base + c); cv[0]=t.x; cv[1]=t.y; cv[2]=t.z; cv[3]=t.w;
    t = *(const float4*)(normst + base + c); nv[0]=t.x; nv[1]=t.y; nv[2]=t.z; nv[3]=t.w;
    t = *(const float4*)(maxst  + base + c); mv[0]=t.x; mv[1]=t.y; mv[2]=t.z; mv[3]=t.w;

    float y[4], cn[4], nn[4], mn[4];
    float s = 0.f, sq = 0.f;
#pragma unroll
    for (int j = 0; j < 4; ++j) {
        float fj  = fv[j];
        float lsf = fminf(fj, 0.f) - log1pf(expf(-fabsf(fj)));
        float lfm = mv[j] + lsf;
        float ij  = iv[j];
        float mnew = fmaxf(ij, lfm);
        float ig = expf(ij  - mnew);
        float fg = expf(lfm - mnew);
        float cnew = fg * cv[j] + ig * tanhf(zv[j]);
        float nnew = fg * nv[j] + ig;
        float so   = 1.f / (1.f + expf(-ov[j]));
        float yj   = so * cnew / (nnew + 1e-6f);
        y[j] = yj; cn[j] = cnew; nn[j] = nnew; mn[j] = mnew;
        s += yj; sq += yj * yj;
    }

    __shared__ float rs[8], rq[8];
    float ws = warpSum(s), wq = warpSum(sq);
    if ((tid & 31) == 0) { rs[tid >> 5] = ws; rq[tid >> 5] = wq; }
    __syncthreads();
    float ts = 0.f, tq = 0.f;
#pragma unroll
    for (int i = 0; i < 8; i++) { ts += rs[i]; tq += rq[i]; }
    const float mean = ts * (1.f / HSZ);
    const float var  = tq * (1.f / HSZ) - mean * mean;
    const float rstd = rsqrtf(var + 1e-5f);

    const int h = n * HSZ + c;
    float4 gw = *(const float4*)(gn_w + h);
    float4 gb = *(const float4*)(gn_b + h);
    float4 xs = *(const float4*)(x + base + c);
    const float gwv[4] = { gw.x, gw.y, gw.z, gw.w };
    const float gbv[4] = { gb.x, gb.y, gb.z, gb.w };
    const float xv4[4] = { xs.x, xs.y, xs.z, xs.w };

    float ot[4];
#pragma unroll
    for (int j = 0; j < 4; ++j)
        ot[j] = (y[j] - mean) * rstd * gwv[j] + gbv[j] + xv4[j];

    *(float4*)(dout + 0 * BH + base + c) = make_float4(ot[0], ot[1], ot[2], ot[3]);
    *(float4*)(dout + 4 * BH + base + c) = make_float4(y[0],  y[1],  y[2],  y[3]);
    *(float4*)(dout + 5 * BH + base + c) = make_float4(cn[0], cn[1], cn[2], cn[3]);
    *(float4*)(dout + 6 * BH + base + c) = make_float4(nn[0], nn[1], nn[2], nn[3]);
    *(float4*)(dout + 7 * BH + base + c) = make_float4(mn[0], mn[1], mn[2], mn[3]);
}

// ---------------- launch -----------------------------------------------------
extern "C" void kernel_launch(void* const* d_in, const int* in_sizes, int n_in,
                              void* d_out, int out_size)
{
    const float* x      = (const float*)d_in[0];
    const float* cs     = (const float*)d_in[1];
    const float* rec    = (const float*)d_in[2];
    const float* cell   = (const float*)d_in[3];
    const float* normst = (const float*)d_in[4];
    const float* maxst  = (const float*)d_in[5];
    const float* ln_w   = (const float*)d_in[6];
    const float* conv_w = (const float*)d_in[7];
    const float* conv_b = (const float*)d_in[8];
    const float* wi_in  = (const float*)d_in[9];
    const float* wf_in  = (const float*)d_in[10];
    const float* wz_in  = (const float*)d_in[11];
    const float* wo_in  = (const float*)d_in[12];
    const float* wi_st  = (const float*)d_in[13];
    const float* wf_st  = (const float*)d_in[14];
    const float* wz_st  = (const float*)d_in[15];
    const float* wo_st  = (const float*)d_in[16];
    const float* bi     = (const float*)d_in[17];
    const float* bf_    = (const float*)d_in[18];
    const float* bz     = (const float*)d_in[19];
    const float* bo     = (const float*)d_in[20];
    const float* gn_w   = (const float*)d_in[21];
    const float* gn_b   = (const float*)d_in[22];
    float* out = (float*)d_out;

    static int smem_set = 0;
    if (!smem_set) {
        cudaFuncSetAttribute(gemm_kernel, cudaFuncAttributeMaxDynamicSharedMemorySize,
                             SMEM_B);
        smem_set = 1;
    }

    ln_conv_kernel<<<BATCH, 256>>>(x, cs, ln_w, conv_w, conv_b,
                                   out + (size_t)BATCH * HDIM);

    convert_w_kernel<<<dim3(4096, 8), 256>>>(wi_in, wf_in, wz_in, wo_in,
                                             wi_st, wf_st, wz_st, wo_st);
    convert_rec_kernel<<<8192, 256>>>(rec);

    dim3 grid(HSZ / BN, BATCH / BM, 16);
    gemm_kernel<<<grid, 256, SMEM_B>>>(bi, bf_, bz, bo);

    gate_kernel<<<BATCH * NHEAD, 256>>>(x, cell, normst, maxst, gn_w, gn_b, out);
}

// round 7
// speedup vs baseline: 1.0935x; 1.0781x over previous
#include <cuda_runtime.h>
#include <cuda_bf16.h>
#include <math.h>
#include <stdint.h>

#define BATCH 2048
#define HDIM  4096
#define NHEAD 4
#define HSZ   1024

#define BM 128
#define BN 256
#define BK 64              // bf16 elems per K-chunk (128B data rows)
#define NCHUNK 32          // 2 passes * (1024/64)
#define NTHR 512

#define TSTRIDE 144        // 128B data + 16B pad; conflict-free for ldmatrix
#define A_TILE_B (128 * TSTRIDE)         // 18432
#define B_TILE_B (256 * TSTRIDE)         // 36864
#define STAGE_B  (2 * A_TILE_B + 2 * B_TILE_B)   // 110592
#define SMEM_B   (2 * STAGE_B)                   // 221184

#define OFF_AH 0
#define OFF_AL A_TILE_B
#define OFF_BH (2 * A_TILE_B)
#define OFF_BL (2 * A_TILE_B + B_TILE_B)

typedef __nv_bfloat16 bf16;

// ---------------- scratch (device globals; no runtime allocation) ----------
__device__ __align__(16) bf16 g_xn_hi  [(size_t)BATCH * HDIM];
__device__ __align__(16) bf16 g_xn_lo  [(size_t)BATCH * HDIM];
__device__ __align__(16) bf16 g_xact_hi[(size_t)BATCH * HDIM];
__device__ __align__(16) bf16 g_xact_lo[(size_t)BATCH * HDIM];
__device__ __align__(16) bf16 g_rec_hi [(size_t)BATCH * HDIM];
__device__ __align__(16) bf16 g_rec_lo [(size_t)BATCH * HDIM];
__device__ __align__(16) bf16 g_w_hi   [8ull * NHEAD * HSZ * HSZ];
__device__ __align__(16) bf16 g_w_lo   [8ull * NHEAD * HSZ * HSZ];
__device__ __align__(16) float g_gates [4ull * BATCH * HDIM];

// ---------------- helpers ---------------------------------------------------
__device__ __forceinline__ float warpSum(float v) {
#pragma unroll
    for (int o = 16; o > 0; o >>= 1) v += __shfl_down_sync(0xffffffffu, v, o);
    return v;
}

__device__ __forceinline__ uint32_t smem_u32(const void* p) {
    uint32_t a;
    asm("{ .reg .u64 t; cvta.to.shared.u64 t, %1; cvt.u32.u64 %0, t; }"
        : "=r"(a) : "l"(p));
    return a;
}

__device__ __forceinline__ void cp16(uint32_t saddr, const void* gaddr) {
    asm volatile("cp.async.cg.shared.global [%0], [%1], 16;"
                 :: "r"(saddr), "l"(gaddr));
}

__device__ __forceinline__ void ldsm4(uint32_t* r, uint32_t a) {
    asm volatile("ldmatrix.sync.aligned.m8n8.x4.shared.b16 {%0,%1,%2,%3}, [%4];"
                 : "=r"(r[0]), "=r"(r[1]), "=r"(r[2]), "=r"(r[3]) : "r"(a));
}

__device__ __forceinline__ void mma_bf16(float* c, const uint32_t* a,
                                         uint32_t b0, uint32_t b1) {
    asm volatile(
        "mma.sync.aligned.m16n8k16.row.col.f32.bf16.bf16.f32 "
        "{%0,%1,%2,%3}, {%4,%5,%6,%7}, {%8,%9}, {%0,%1,%2,%3};"
        : "+f"(c[0]), "+f"(c[1]), "+f"(c[2]), "+f"(c[3])
        : "r"(a[0]), "r"(a[1]), "r"(a[2]), "r"(a[3]), "r"(b0), "r"(b1));
}

__device__ __forceinline__ void split_bf16(float x, bf16& h, bf16& l) {
    h = __float2bfloat16(x);
    l = __float2bfloat16(x - __bfloat162float(h));
}

// ---------------- Kernel A: layernorm + conv + silu + hi/lo emit -----------
__global__ __launch_bounds__(256) void ln_conv_kernel(
    const float* __restrict__ x, const float* __restrict__ cs,
    const float* __restrict__ ln_w, const float* __restrict__ conv_w,
    const float* __restrict__ conv_b, float* __restrict__ out_ncs)
{
    const int b   = blockIdx.x;
    const int tid = threadIdx.x;
    const float* xr = x + (size_t)b * HDIM;

    float4 xv[4];
    float s = 0.f, sq = 0.f;
#pragma unroll
    for (int i = 0; i < 4; i++) {
        xv[i] = *(const float4*)(xr + (size_t)(tid + i * 256) * 4);
        s  += xv[i].x + xv[i].y + xv[i].z + xv[i].w;
        sq += xv[i].x * xv[i].x + xv[i].y * xv[i].y + xv[i].z * xv[i].z + xv[i].w * xv[i].w;
    }
    __shared__ float rs[8], rq[8];
    float ws = warpSum(s), wq = warpSum(sq);
    if ((tid & 31) == 0) { rs[tid >> 5] = ws; rq[tid >> 5] = wq; }
    __syncthreads();
    float ts = 0.f, tq = 0.f;
#pragma unroll
    for (int i = 0; i < 8; i++) { ts += rs[i]; tq += rq[i]; }
    const float mean = ts * (1.f / HDIM);
    const float var  = tq * (1.f / HDIM) - mean * mean;
    const float rstd = rsqrtf(var + 1e-5f);

    const float* csb = cs      + (size_t)b * 3 * HDIM;
    float*       ncs = out_ncs + (size_t)b * 3 * HDIM;

#pragma unroll
    for (int i = 0; i < 4; i++) {
        const int c = (tid + i * 256) * 4;
        float4 lw = *(const float4*)(ln_w + c);
        float4 xn;
        xn.x = (xv[i].x - mean) * rstd * lw.x;
        xn.y = (xv[i].y - mean) * rstd * lw.y;
        xn.z = (xv[i].z - mean) * rstd * lw.z;
        xn.w = (xv[i].w - mean) * rstd * lw.w;

        float4 c0 = *(const float4*)(csb + c);
        float4 c1 = *(const float4*)(csb + HDIM + c);
        float4 c2 = *(const float4*)(csb + 2 * HDIM + c);
        float4 cb = *(const float4*)(conv_b + c);
        float4 w0 = *(const float4*)(conv_w + (size_t)(c + 0) * 4);
        float4 w1 = *(const float4*)(conv_w + (size_t)(c + 1) * 4);
        float4 w2 = *(const float4*)(conv_w + (size_t)(c + 2) * 4);
        float4 w3 = *(const float4*)(conv_w + (size_t)(c + 3) * 4);

        float4 xc;
        xc.x = c0.x * w0.x + c1.x * w0.y + c2.x * w0.z + xn.x * w0.w + cb.x;
        xc.y = c0.y * w1.x + c1.y * w1.y + c2.y * w1.z + xn.y * w1.w + cb.y;
        xc.z = c0.z * w2.x + c1.z * w2.y + c2.z * w2.z + xn.z * w2.w + cb.z;
        xc.w = c0.w * w3.x + c1.w * w3.y + c2.w * w3.z + xn.w * w3.w + cb.w;

        float4 xa;
        xa.x = xc.x / (1.f + expf(-xc.x));
        xa.y = xc.y / (1.f + expf(-xc.y));
        xa.z = xc.z / (1.f + expf(-xc.z));
        xa.w = xc.w / (1.f + expf(-xc.w));

        union { bf16 bb[4]; uint2 u; } nh, nl, ah, al;
        split_bf16(xn.x, nh.bb[0], nl.bb[0]); split_bf16(xn.y, nh.bb[1], nl.bb[1]);
        split_bf16(xn.z, nh.bb[2], nl.bb[2]); split_bf16(xn.w, nh.bb[3], nl.bb[3]);
        split_bf16(xa.x, ah.bb[0], al.bb[0]); split_bf16(xa.y, ah.bb[1], al.bb[1]);
        split_bf16(xa.z, ah.bb[2], al.bb[2]); split_bf16(xa.w, ah.bb[3], al.bb[3]);

        const size_t off = (size_t)b * HDIM + c;
        *(uint2*)(g_xn_hi   + off) = nh.u;
        *(uint2*)(g_xn_lo   + off) = nl.u;
        *(uint2*)(g_xact_hi + off) = ah.u;
        *(uint2*)(g_xact_lo + off) = al.u;

        *(float4*)(ncs + c)            = c1;
        *(float4*)(ncs + HDIM + c)     = c2;
        *(float4*)(ncs + 2 * HDIM + c) = xn;
    }
}

// ---------------- conversion kernels ----------------------------------------
__global__ __launch_bounds__(256) void convert_w_kernel(
    const float* __restrict__ w0, const float* __restrict__ w1,
    const float* __restrict__ w2, const float* __restrict__ w3,
    const float* __restrict__ w4, const float* __restrict__ w5,
    const float* __restrict__ w6, const float* __restrict__ w7)
{
    const float* srcs[8] = { w0, w1, w2, w3, w4, w5, w6, w7 };
    const float* s = srcs[blockIdx.y];
    const size_t base4 = (size_t)blockIdx.y * (NHEAD * HSZ * (HSZ / 4));
    const int i = blockIdx.x * 256 + threadIdx.x;
    float4 v = ((const float4*)s)[i];
    union { bf16 bb[4]; uint2 u; } h, l;
    split_bf16(v.x, h.bb[0], l.bb[0]); split_bf16(v.y, h.bb[1], l.bb[1]);
    split_bf16(v.z, h.bb[2], l.bb[2]); split_bf16(v.w, h.bb[3], l.bb[3]);
    ((uint2*)g_w_hi)[base4 + i] = h.u;
    ((uint2*)g_w_lo)[base4 + i] = l.u;
}

__global__ __launch_bounds__(256) void convert_rec_kernel(const float* __restrict__ src)
{
    const int i = blockIdx.x * 256 + threadIdx.x;
    float4 v = ((const float4*)src)[i];
    union { bf16 bb[4]; uint2 u; } h, l;
    split_bf16(v.x, h.bb[0], l.bb[0]); split_bf16(v.y, h.bb[1], l.bb[1]);
    split_bf16(v.z, h.bb[2], l.bb[2]); split_bf16(v.w, h.bb[3], l.bb[3]);
    ((uint2*)g_rec_hi)[i] = h.u;
    ((uint2*)g_rec_lo)[i] = l.u;
}

// ---------------- Kernel B: HMMA bf16-split GEMM (128x256, 16 warps) -------
__global__ __launch_bounds__(NTHR, 1) void gemm_kernel(
    const float* __restrict__ bi, const float* __restrict__ bf_,
    const float* __restrict__ bz, const float* __restrict__ bo)
{
    extern __shared__ __align__(1024) char smem[];
    const uint32_t sbase = smem_u32(smem);
    const int tid  = threadIdx.x;
    const int wid  = tid >> 5;
    const int lane = tid & 31;

    const int g  = blockIdx.z >> 2;
    const int nh = blockIdx.z & 3;
    const int m0 = blockIdx.y * BM;
    const int n0 = blockIdx.x * BN;

    const bf16* aHi0 = (g < 2 ? g_xact_hi : g_xn_hi);
    const bf16* aLo0 = (g < 2 ? g_xact_lo : g_xn_lo);
    const size_t wb0 = ((size_t)g)       * NHEAD * HSZ * HSZ + (size_t)nh * HSZ * HSZ;
    const size_t wb1 = ((size_t)(g + 4)) * NHEAD * HSZ * HSZ + (size_t)nh * HSZ * HSZ;

    // loader: 12 cp16 per thread per chunk (A: 2 iters, B: 4 iters)
    auto load_chunk = [&](int c) {
        const int pass = c >> 4;
        const int kt   = (c & 15) * BK;
        const uint32_t st = sbase + (uint32_t)(c & 1) * STAGE_B;
        const bf16* aH = (pass ? g_rec_hi : aHi0);
        const bf16* aL = (pass ? g_rec_lo : aLo0);
        const bf16* wH = g_w_hi + (pass ? wb1 : wb0);
        const bf16* wL = g_w_lo + (pass ? wb1 : wb0);
#pragma unroll
        for (int t = 0; t < 2; t++) {
            const int idx = tid + t * NTHR;         // 0..1023
            const int row = idx >> 3;
            const int sec = idx & 7;
            const uint32_t sdst = st + (uint32_t)row * TSTRIDE + sec * 16;
            const size_t aoff = (size_t)(m0 + row) * HDIM + (size_t)nh * HSZ + kt + sec * 8;
            cp16(sdst + OFF_AH, aH + aoff);
            cp16(sdst + OFF_AL, aL + aoff);
        }
#pragma unroll
        for (int t = 0; t < 4; t++) {
            const int idx = tid + t * NTHR;         // 0..2047
            const int row = idx >> 3;               // 0..255
            const int sec = idx & 7;
            const uint32_t sdst = st + (uint32_t)row * TSTRIDE + sec * 16;
            const size_t boff = (size_t)(n0 + row) * HSZ + kt + sec * 8;
            cp16(sdst + OFF_BH, wH + boff);
            cp16(sdst + OFF_BL, wL + boff);
        }
        asm volatile("cp.async.commit_group;");
    };

    // warp tiling: 4 warps along M (32 rows), 4 along N (64 cols)
    const int wm = wid & 3;
    const int wn = wid >> 2;

    const uint32_t aRowOff = (uint32_t)(wm * 32 + (lane & 15)) * TSTRIDE + ((lane >> 4) << 4);
    const uint32_t bRowOff = (uint32_t)(wn * 64 + (lane & 7) + ((lane >> 4) << 3)) * TSTRIDE
                             + (((lane >> 3) & 1) << 4);

    float acc[2][8][4];
#pragma unroll
    for (int mi = 0; mi < 2; mi++)
#pragma unroll
        for (int j = 0; j < 8; j++)
#pragma unroll
            for (int q = 0; q < 4; q++) acc[mi][j][q] = 0.f;

    load_chunk(0);

#pragma unroll 1
    for (int c = 0; c < NCHUNK; c++) {
        asm volatile("cp.async.wait_group 0;");   // chunk c landed
        __syncthreads();                          // all warps done computing c-1
        if (c + 1 < NCHUNK) load_chunk(c + 1);    // into stage (c+1)&1, safe now

        const uint32_t st = sbase + (uint32_t)(c & 1) * STAGE_B;
#pragma unroll
        for (int kk = 0; kk < 4; kk++) {
            uint32_t ah[2][4], al[2][4];
            const uint32_t ka = st + aRowOff + kk * 32;
            ldsm4(ah[0], ka + OFF_AH);
            ldsm4(ah[1], ka + OFF_AH + 16 * TSTRIDE);
            ldsm4(al[0], ka + OFF_AL);
            ldsm4(al[1], ka + OFF_AL + 16 * TSTRIDE);

            uint32_t Bh[4][4], Bl[4][4];
#pragma unroll
            for (int jj = 0; jj < 4; jj++) {
                const uint32_t kb = st + bRowOff + jj * 16 * TSTRIDE + kk * 32;
                ldsm4(Bh[jj], kb + OFF_BH);
                ldsm4(Bl[jj], kb + OFF_BL);
            }
            // term hi*hi
#pragma unroll
            for (int jj = 0; jj < 4; jj++)
#pragma unroll
                for (int mi = 0; mi < 2; mi++) {
                    mma_bf16(acc[mi][2 * jj],     ah[mi], Bh[jj][0], Bh[jj][1]);
                    mma_bf16(acc[mi][2 * jj + 1], ah[mi], Bh[jj][2], Bh[jj][3]);
                }
            // term hi*lo
#pragma unroll
            for (int jj = 0; jj < 4; jj++)
#pragma unroll
                for (int mi = 0; mi < 2; mi++) {
                    mma_bf16(acc[mi][2 * jj],     ah[mi], Bl[jj][0], Bl[jj][1]);
                    mma_bf16(acc[mi][2 * jj + 1], ah[mi], Bl[jj][2], Bl[jj][3]);
                }
            // term lo*hi
#pragma unroll
            for (int jj = 0; jj < 4; jj++)
#pragma unroll
                for (int mi = 0; mi < 2; mi++) {
                    mma_bf16(acc[mi][2 * jj],     al[mi], Bh[jj][0], Bh[jj][1]);
                    mma_bf16(acc[mi][2 * jj + 1], al[mi], Bh[jj][2], Bh[jj][3]);
                }
        }
    }

    // epilogue: add bias, write gates
    const float* bias = (g == 0) ? bi : (g == 1) ? bf_ : (g == 2) ? bz : bo;
    float* gbase = g_gates + (size_t)g * BATCH * HDIM;

#pragma unroll
    for (int mi = 0; mi < 2; mi++) {
        const int row0 = m0 + wm * 32 + mi * 16 + (lane >> 2);
#pragma unroll
        for (int j = 0; j < 8; j++) {
            const int col = n0 + wn * 64 + j * 8 + (lane & 3) * 2;
            const int h   = nh * HSZ + col;
            const float b0 = bias[h], b1 = bias[h + 1];
            float* p0 = gbase + (size_t)row0 * HDIM + h;
            float* p1 = p0 + 8 * HDIM;
            *(float2*)p0 = make_float2(acc[mi][j][0] + b0, acc[mi][j][1] + b1);
            *(float2*)p1 = make_float2(acc[mi][j][2] + b0, acc[mi][j][3] + b1);
        }
    }
}

// ---------------- Kernel C: gate math + group norm + outputs ---------------
__global__ __launch_bounds__(256) void gate_kernel(
    const float* __restrict__ x,      const float* __restrict__ cell,
    const float* __restrict__ normst, const float* __restrict__ maxst,
    const float* __restrict__ gn_w,   const float* __restrict__ gn_b,
    float* __restrict__ dout)
{
    const int blk = blockIdx.x;
    const int b = blk >> 2, n = blk & 3;
    const int tid = threadIdx.x;
    const size_t BH = (size_t)BATCH * HDIM;
    const size_t base = (size_t)b * HDIM + n * HSZ;
    const int c = tid * 4;

    float4 t;
    float iv[4], fv[4], zv[4], ov[4], cv[4], nv[4], mv[4];
    t = *(const float4*)(g_gates + 0 * BH + base + c); iv[0]=t.x; iv[1]=t.y; iv[2]=t.z; iv[3]=t.w;
    t = *(const float4*)(g_gates + 1 * BH + base + c); fv[0]=t.x; fv[1]=t.y; fv[2]=t.z; fv[3]=t.w;
    t = *(const float4*)(g_gates + 2 * BH + base + c); zv[0]=t.x; zv[1]=t.y; zv[2]=t.z; zv[3]=t.w;
    t = *(const float4*)(g_gates + 3 * BH + base + c); ov[0]=t.x; ov[1]=t.y; ov[2]=t.z; ov[3]=t.w;
    t = *(const float4*)(cell   + base + c); cv[0]=t.x; cv[1]=t.y; cv[2]=t.z; cv[3]=t.w;
    t = *(const float4*)(normst + base + c); nv[0]=t.x; nv[1]=t.y; nv[2]=t.z; nv[3]=t.w;
    t = *(const float4*)(maxst  + base + c); mv[0]=t.x; mv[1]=t.y; mv[2]=t.z; mv[3]=t.w;

    float y[4], cn[4], nn[4], mn[4];
    float s = 0.f, sq = 0.f;
#pragma unroll
    for (int j = 0; j < 4; ++j) {
        float fj  = fv[j];
        float lsf = fminf(fj, 0.f) - log1pf(expf(-fabsf(fj)));
        float lfm = mv[j] + lsf;
        float ij  = iv[j];
        float mnew = fmaxf(ij, lfm);
        float ig = expf(ij  - mnew);
        float fg = expf(lfm - mnew);
        float cnew = fg * cv[j] + ig * tanhf(zv[j]);
        float nnew = fg * nv[j] + ig;
        float so   = 1.f / (1.f + expf(-ov[j]));
        float yj   = so * cnew / (nnew + 1e-6f);
        y[j] = yj; cn[j] = cnew; nn[j] = nnew; mn[j] = mnew;
        s += yj; sq += yj * yj;
    }

    __shared__ float rs[8], rq[8];
    float ws = warpSum(s), wq = warpSum(sq);
    if ((tid & 31) == 0) { rs[tid >> 5] = ws; rq[tid >> 5] = wq; }
    __syncthreads();
    float ts = 0.f, tq = 0.f;
#pragma unroll
    for (int i = 0; i < 8; i++) { ts += rs[i]; tq += rq[i]; }
    const float mean = ts * (1.f / HSZ);
    const float var  = tq * (1.f / HSZ) - mean * mean;
    const float rstd = rsqrtf(var + 1e-5f);

    const int h = n * HSZ + c;
    float4 gw = *(const float4*)(gn_w + h);
    float4 gb = *(const float4*)(gn_b + h);
    float4 xs = *(const float4*)(x + base + c);
    const float gwv[4] = { gw.x, gw.y, gw.z, gw.w };
    const float gbv[4] = { gb.x, gb.y, gb.z, gb.w };
    const float xv4[4] = { xs.x, xs.y, xs.z, xs.w };

    float ot[4];
#pragma unroll
    for (int j = 0; j < 4; ++j)
        ot[j] = (y[j] - mean) * rstd * gwv[j] + gbv[j] + xv4[j];

    *(float4*)(dout + 0 * BH + base + c) = make_float4(ot[0], ot[1], ot[2], ot[3]);
    *(float4*)(dout + 4 * BH + base + c) = make_float4(y[0],  y[1],  y[2],  y[3]);
    *(float4*)(dout + 5 * BH + base + c) = make_float4(cn[0], cn[1], cn[2], cn[3]);
    *(float4*)(dout + 6 * BH + base + c) = make_float4(nn[0], nn[1], nn[2], nn[3]);
    *(float4*)(dout + 7 * BH + base + c) = make_float4(mn[0], mn[1], mn[2], mn[3]);
}

// ---------------- launch -----------------------------------------------------
extern "C" void kernel_launch(void* const* d_in, const int* in_sizes, int n_in,
                              void* d_out, int out_size)
{
    const float* x      = (const float*)d_in[0];
    const float* cs     = (const float*)d_in[1];
    const float* rec    = (const float*)d_in[2];
    const float* cell   = (const float*)d_in[3];
    const float* normst = (const float*)d_in[4];
    const float* maxst  = (const float*)d_in[5];
    const float* ln_w   = (const float*)d_in[6];
    const float* conv_w = (const float*)d_in[7];
    const float* conv_b = (const float*)d_in[8];
    const float* wi_in  = (const float*)d_in[9];
    const float* wf_in  = (const float*)d_in[10];
    const float* wz_in  = (const float*)d_in[11];
    const float* wo_in  = (const float*)d_in[12];
    const float* wi_st  = (const float*)d_in[13];
    const float* wf_st  = (const float*)d_in[14];
    const float* wz_st  = (const float*)d_in[15];
    const float* wo_st  = (const float*)d_in[16];
    const float* bi     = (const float*)d_in[17];
    const float* bf_    = (const float*)d_in[18];
    const float* bz     = (const float*)d_in[19];
    const float* bo     = (const float*)d_in[20];
    const float* gn_w   = (const float*)d_in[21];
    const float* gn_b   = (const float*)d_in[22];
    float* out = (float*)d_out;

    static int smem_set = 0;
    if (!smem_set) {
        cudaFuncSetAttribute(gemm_kernel, cudaFuncAttributeMaxDynamicSharedMemorySize,
                             SMEM_B);
        smem_set = 1;
    }

    ln_conv_kernel<<<BATCH, 256>>>(x, cs, ln_w, conv_w, conv_b,
                                   out + (size_t)BATCH * HDIM);

    convert_w_kernel<<<dim3(4096, 8), 256>>>(wi_in, wf_in, wz_in, wo_in,
                                             wi_st, wf_st, wz_st, wo_st);
    convert_rec_kernel<<<8192, 256>>>(rec);

    dim3 grid(HSZ / BN, BATCH / BM, 16);
    gemm_kernel<<<grid, NTHR, SMEM_B>>>(bi, bf_, bz, bo);

    gate_kernel<<<BATCH * NHEAD, 256>>>(x, cell, normst, maxst, gn_w, gn_b, out);
}

// round 8
// speedup vs baseline: 1.1334x; 1.0365x over previous
#include <cuda_runtime.h>
#include <cuda_bf16.h>
#include <math.h>
#include <stdint.h>

#define BATCH 2048
#define HDIM  4096
#define NHEAD 4
#define HSZ   1024

#define BM 128
#define BN 256
#define BK 64              // bf16 elems per K-chunk (128B data rows)
#define NCHUNK 32          // 2 passes * (1024/64)
#define NTHR 256           // 8 warps, 64x64 per warp

#define TSTRIDE 144        // 128B data + 16B pad; conflict-free for ldmatrix
#define A_TILE_B (128 * TSTRIDE)         // 18432
#define B_TILE_B (256 * TSTRIDE)         // 36864
#define STAGE_B  (2 * A_TILE_B + 2 * B_TILE_B)   // 110592
#define SMEM_B   (2 * STAGE_B)                   // 221184

#define OFF_AH 0
#define OFF_AL A_TILE_B
#define OFF_BH (2 * A_TILE_B)
#define OFF_BL (2 * A_TILE_B + B_TILE_B)

typedef __nv_bfloat16 bf16;

// ---------------- scratch (device globals; no runtime allocation) ----------
__device__ __align__(16) bf16 g_xn_hi  [(size_t)BATCH * HDIM];
__device__ __align__(16) bf16 g_xn_lo  [(size_t)BATCH * HDIM];
__device__ __align__(16) bf16 g_xact_hi[(size_t)BATCH * HDIM];
__device__ __align__(16) bf16 g_xact_lo[(size_t)BATCH * HDIM];
__device__ __align__(16) bf16 g_rec_hi [(size_t)BATCH * HDIM];
__device__ __align__(16) bf16 g_rec_lo [(size_t)BATCH * HDIM];
__device__ __align__(16) bf16 g_w_hi   [8ull * NHEAD * HSZ * HSZ];
__device__ __align__(16) bf16 g_w_lo   [8ull * NHEAD * HSZ * HSZ];
__device__ __align__(16) float g_gates [4ull * BATCH * HDIM];

// ---------------- helpers ---------------------------------------------------
__device__ __forceinline__ float warpSum(float v) {
#pragma unroll
    for (int o = 16; o > 0; o >>= 1) v += __shfl_down_sync(0xffffffffu, v, o);
    return v;
}

__device__ __forceinline__ uint32_t smem_u32(const void* p) {
    uint32_t a;
    asm("{ .reg .u64 t; cvta.to.shared.u64 t, %1; cvt.u32.u64 %0, t; }"
        : "=r"(a) : "l"(p));
    return a;
}

__device__ __forceinline__ void cp16(uint32_t saddr, const void* gaddr) {
    asm volatile("cp.async.cg.shared.global [%0], [%1], 16;"
                 :: "r"(saddr), "l"(gaddr));
}

__device__ __forceinline__ void ldsm4(uint32_t* r, uint32_t a) {
    asm volatile("ldmatrix.sync.aligned.m8n8.x4.shared.b16 {%0,%1,%2,%3}, [%4];"
                 : "=r"(r[0]), "=r"(r[1]), "=r"(r[2]), "=r"(r[3]) : "r"(a));
}

__device__ __forceinline__ void mma_bf16(float* c, const uint32_t* a,
                                         uint32_t b0, uint32_t b1) {
    asm volatile(
        "mma.sync.aligned.m16n8k16.row.col.f32.bf16.bf16.f32 "
        "{%0,%1,%2,%3}, {%4,%5,%6,%7}, {%8,%9}, {%0,%1,%2,%3};"
        : "+f"(c[0]), "+f"(c[1]), "+f"(c[2]), "+f"(c[3])
        : "r"(a[0]), "r"(a[1]), "r"(a[2]), "r"(a[3]), "r"(b0), "r"(b1));
}

__device__ __forceinline__ void split_bf16(float x, bf16& h, bf16& l) {
    h = __float2bfloat16(x);
    l = __float2bfloat16(x - __bfloat162float(h));
}

// ---------------- Kernel A: layernorm + conv + silu + hi/lo emit -----------
__global__ __launch_bounds__(256) void ln_conv_kernel(
    const float* __restrict__ x, const float* __restrict__ cs,
    const float* __restrict__ ln_w, const float* __restrict__ conv_w,
    const float* __restrict__ conv_b, float* __restrict__ out_ncs)
{
    const int b   = blockIdx.x;
    const int tid = threadIdx.x;
    const float* xr = x + (size_t)b * HDIM;

    float4 xv[4];
    float s = 0.f, sq = 0.f;
#pragma unroll
    for (int i = 0; i < 4; i++) {
        xv[i] = *(const float4*)(xr + (size_t)(tid + i * 256) * 4);
        s  += xv[i].x + xv[i].y + xv[i].z + xv[i].w;
        sq += xv[i].x * xv[i].x + xv[i].y * xv[i].y + xv[i].z * xv[i].z + xv[i].w * xv[i].w;
    }
    __shared__ float rs[8], rq[8];
    float ws = warpSum(s), wq = warpSum(sq);
    if ((tid & 31) == 0) { rs[tid >> 5] = ws; rq[tid >> 5] = wq; }
    __syncthreads();
    float ts = 0.f, tq = 0.f;
#pragma unroll
    for (int i = 0; i < 8; i++) { ts += rs[i]; tq += rq[i]; }
    const float mean = ts * (1.f / HDIM);
    const float var  = tq * (1.f / HDIM) - mean * mean;
    const float rstd = rsqrtf(var + 1e-5f);

    const float* csb = cs      + (size_t)b * 3 * HDIM;
    float*       ncs = out_ncs + (size_t)b * 3 * HDIM;

#pragma unroll
    for (int i = 0; i < 4; i++) {
        const int c = (tid + i * 256) * 4;
        float4 lw = *(const float4*)(ln_w + c);
        float4 xn;
        xn.x = (xv[i].x - mean) * rstd * lw.x;
        xn.y = (xv[i].y - mean) * rstd * lw.y;
        xn.z = (xv[i].z - mean) * rstd * lw.z;
        xn.w = (xv[i].w - mean) * rstd * lw.w;

        float4 c0 = *(const float4*)(csb + c);
        float4 c1 = *(const float4*)(csb + HDIM + c);
        float4 c2 = *(const float4*)(csb + 2 * HDIM + c);
        float4 cb = *(const float4*)(conv_b + c);
        float4 w0 = *(const float4*)(conv_w + (size_t)(c + 0) * 4);
        float4 w1 = *(const float4*)(conv_w + (size_t)(c + 1) * 4);
        float4 w2 = *(const float4*)(conv_w + (size_t)(c + 2) * 4);
        float4 w3 = *(const float4*)(conv_w + (size_t)(c + 3) * 4);

        float4 xc;
        xc.x = c0.x * w0.x + c1.x * w0.y + c2.x * w0.z + xn.x * w0.w + cb.x;
        xc.y = c0.y * w1.x + c1.y * w1.y + c2.y * w1.z + xn.y * w1.w + cb.y;
        xc.z = c0.z * w2.x + c1.z * w2.y + c2.z * w2.z + xn.z * w2.w + cb.z;
        xc.w = c0.w * w3.x + c1.w * w3.y + c2.w * w3.z + xn.w * w3.w + cb.w;

        float4 xa;
        xa.x = xc.x / (1.f + expf(-xc.x));
        xa.y = xc.y / (1.f + expf(-xc.y));
        xa.z = xc.z / (1.f + expf(-xc.z));
        xa.w = xc.w / (1.f + expf(-xc.w));

        union { bf16 bb[4]; uint2 u; } nh, nl, ah, al;
        split_bf16(xn.x, nh.bb[0], nl.bb[0]); split_bf16(xn.y, nh.bb[1], nl.bb[1]);
        split_bf16(xn.z, nh.bb[2], nl.bb[2]); split_bf16(xn.w, nh.bb[3], nl.bb[3]);
        split_bf16(xa.x, ah.bb[0], al.bb[0]); split_bf16(xa.y, ah.bb[1], al.bb[1]);
        split_bf16(xa.z, ah.bb[2], al.bb[2]); split_bf16(xa.w, ah.bb[3], al.bb[3]);

        const size_t off = (size_t)b * HDIM + c;
        *(uint2*)(g_xn_hi   + off) = nh.u;
        *(uint2*)(g_xn_lo   + off) = nl.u;
        *(uint2*)(g_xact_hi + off) = ah.u;
        *(uint2*)(g_xact_lo + off) = al.u;

        *(float4*)(ncs + c)            = c1;
        *(float4*)(ncs + HDIM + c)     = c2;
        *(float4*)(ncs + 2 * HDIM + c) = xn;
    }
}

// ---------------- conversion kernels ----------------------------------------
__global__ __launch_bounds__(256) void convert_w_kernel(
    const float* __restrict__ w0, const float* __restrict__ w1,
    const float* __restrict__ w2, const float* __restrict__ w3,
    const float* __restrict__ w4, const float* __restrict__ w5,
    const float* __restrict__ w6, const float* __restrict__ w7)
{
    const float* srcs[8] = { w0, w1, w2, w3, w4, w5, w6, w7 };
    const float* s = srcs[blockIdx.y];
    const size_t base4 = (size_t)blockIdx.y * (NHEAD * HSZ * (HSZ / 4));
    const int i = blockIdx.x * 256 + threadIdx.x;
    float4 v = ((const float4*)s)[i];
    union { bf16 bb[4]; uint2 u; } h, l;
    split_bf16(v.x, h.bb[0], l.bb[0]); split_bf16(v.y, h.bb[1], l.bb[1]);
    split_bf16(v.z, h.bb[2], l.bb[2]); split_bf16(v.w, h.bb[3], l.bb[3]);
    ((uint2*)g_w_hi)[base4 + i] = h.u;
    ((uint2*)g_w_lo)[base4 + i] = l.u;
}

__global__ __launch_bounds__(256) void convert_rec_kernel(const float* __restrict__ src)
{
    const int i = blockIdx.x * 256 + threadIdx.x;
    float4 v = ((const float4*)src)[i];
    union { bf16 bb[4]; uint2 u; } h, l;
    split_bf16(v.x, h.bb[0], l.bb[0]); split_bf16(v.y, h.bb[1], l.bb[1]);
    split_bf16(v.z, h.bb[2], l.bb[2]); split_bf16(v.w, h.bb[3], l.bb[3]);
    ((uint2*)g_rec_hi)[i] = h.u;
    ((uint2*)g_rec_lo)[i] = l.u;
}

// ---------------- Kernel B: HMMA bf16-split GEMM (8 warps, 64x64/warp) -----
__global__ __launch_bounds__(NTHR, 1) void gemm_kernel(
    const float* __restrict__ bi, const float* __restrict__ bf_,
    const float* __restrict__ bz, const float* __restrict__ bo)
{
    extern __shared__ __align__(1024) char smem[];
    const uint32_t sbase = smem_u32(smem);
    const int tid  = threadIdx.x;
    const int wid  = tid >> 5;
    const int lane = tid & 31;

    const int g  = blockIdx.z >> 2;
    const int nh = blockIdx.z & 3;
    const int m0 = blockIdx.y * BM;
    const int n0 = blockIdx.x * BN;

    const bf16* aHi0 = (g < 2 ? g_xact_hi : g_xn_hi);
    const bf16* aLo0 = (g < 2 ? g_xact_lo : g_xn_lo);
    const size_t wb0 = ((size_t)g)       * NHEAD * HSZ * HSZ + (size_t)nh * HSZ * HSZ;
    const size_t wb1 = ((size_t)(g + 4)) * NHEAD * HSZ * HSZ + (size_t)nh * HSZ * HSZ;

    // loader: 24 cp16 per thread per chunk (A: 4 iters, B: 8 iters)
    auto load_chunk = [&](int c) {
        const int pass = c >> 4;
        const int kt   = (c & 15) * BK;
        const uint32_t st = sbase + (uint32_t)(c & 1) * STAGE_B;
        const bf16* aH = (pass ? g_rec_hi : aHi0);
        const bf16* aL = (pass ? g_rec_lo : aLo0);
        const bf16* wH = g_w_hi + (pass ? wb1 : wb0);
        const bf16* wL = g_w_lo + (pass ? wb1 : wb0);
#pragma unroll
        for (int t = 0; t < 4; t++) {
            const int idx = tid + t * NTHR;         // 0..1023
            const int row = idx >> 3;
            const int sec = idx & 7;
            const uint32_t sdst = st + (uint32_t)row * TSTRIDE + sec * 16;
            const size_t aoff = (size_t)(m0 + row) * HDIM + (size_t)nh * HSZ + kt + sec * 8;
            cp16(sdst + OFF_AH, aH + aoff);
            cp16(sdst + OFF_AL, aL + aoff);
        }
#pragma unroll
        for (int t = 0; t < 8; t++) {
            const int idx = tid + t * NTHR;         // 0..2047
            const int row = idx >> 3;               // 0..255
            const int sec = idx & 7;
            const uint32_t sdst = st + (uint32_t)row * TSTRIDE + sec * 16;
            const size_t boff = (size_t)(n0 + row) * HSZ + kt + sec * 8;
            cp16(sdst + OFF_BH, wH + boff);
            cp16(sdst + OFF_BL, wL + boff);
        }
        asm volatile("cp.async.commit_group;");
    };

    // warp tiling: 2 warps along M (64 rows), 4 along N (64 cols)
    const int wm = wid & 1;
    const int wn = wid >> 1;

    const uint32_t aRowOff = (uint32_t)(wm * 64 + (lane & 15)) * TSTRIDE + ((lane >> 4) << 4);
    const uint32_t bRowOff = (uint32_t)(wn * 64 + (lane & 7) + ((lane >> 4) << 3)) * TSTRIDE
                             + (((lane >> 3) & 1) << 4);

    float acc[4][8][4];
#pragma unroll
    for (int mi = 0; mi < 4; mi++)
#pragma unroll
        for (int j = 0; j < 8; j++)
#pragma unroll
            for (int q = 0; q < 4; q++) acc[mi][j][q] = 0.f;

    load_chunk(0);

#pragma unroll 1
    for (int c = 0; c < NCHUNK; c++) {
        asm volatile("cp.async.wait_group 0;");   // chunk c landed
        __syncthreads();                          // all warps done computing c-1
        if (c + 1 < NCHUNK) load_chunk(c + 1);    // into other stage, safe now

        const uint32_t st = sbase + (uint32_t)(c & 1) * STAGE_B;
#pragma unroll
        for (int kk = 0; kk < 4; kk++) {
            const uint32_t ka = st + aRowOff + kk * 32;

            uint32_t ah[4][4], Bh[4][4];
#pragma unroll
            for (int mi = 0; mi < 4; mi++)
                ldsm4(ah[mi], ka + OFF_AH + mi * 16 * TSTRIDE);
#pragma unroll
            for (int jj = 0; jj < 4; jj++) {
                const uint32_t kb = st + bRowOff + jj * 16 * TSTRIDE + kk * 32;
                ldsm4(Bh[jj], kb + OFF_BH);
            }
            // term hi*hi
#pragma unroll
            for (int jj = 0; jj < 4; jj++)
#pragma unroll
                for (int mi = 0; mi < 4; mi++) {
                    mma_bf16(acc[mi][2 * jj],     ah[mi], Bh[jj][0], Bh[jj][1]);
                    mma_bf16(acc[mi][2 * jj + 1], ah[mi], Bh[jj][2], Bh[jj][3]);
                }
            // term hi*lo
            uint32_t Bl[4][4];
#pragma unroll
            for (int jj = 0; jj < 4; jj++) {
                const uint32_t kb = st + bRowOff + jj * 16 * TSTRIDE + kk * 32;
                ldsm4(Bl[jj], kb + OFF_BL);
            }
#pragma unroll
            for (int jj = 0; jj < 4; jj++)
#pragma unroll
                for (int mi = 0; mi < 4; mi++) {
                    mma_bf16(acc[mi][2 * jj],     ah[mi], Bl[jj][0], Bl[jj][1]);
                    mma_bf16(acc[mi][2 * jj + 1], ah[mi], Bl[jj][2], Bl[jj][3]);
                }
            // term lo*hi (ah dead, Bl dead)
            uint32_t al[4][4];
#pragma unroll
            for (int mi = 0; mi < 4; mi++)
                ldsm4(al[mi], ka + OFF_AL + mi * 16 * TSTRIDE);
#pragma unroll
            for (int jj = 0; jj < 4; jj++)
#pragma unroll
                for (int mi = 0; mi < 4; mi++) {
                    mma_bf16(acc[mi][2 * jj],     al[mi], Bh[jj][0], Bh[jj][1]);
                    mma_bf16(acc[mi][2 * jj + 1], al[mi], Bh[jj][2], Bh[jj][3]);
                }
        }
    }

    // epilogue: add bias, write gates
    const float* bias = (g == 0) ? bi : (g == 1) ? bf_ : (g == 2) ? bz : bo;
    float* gbase = g_gates + (size_t)g * BATCH * HDIM;

#pragma unroll
    for (int mi = 0; mi < 4; mi++) {
        const int row0 = m0 + wm * 64 + mi * 16 + (lane >> 2);
#pragma unroll
        for (int j = 0; j < 8; j++) {
            const int col = n0 + wn * 64 + j * 8 + (lane & 3) * 2;
            const int h   = nh * HSZ + col;
            const float b0 = bias[h], b1 = bias[h + 1];
            float* p0 = gbase + (size_t)row0 * HDIM + h;
            float* p1 = p0 + 8 * HDIM;
            *(float2*)p0 = make_float2(acc[mi][j][0] + b0, acc[mi][j][1] + b1);
            *(float2*)p1 = make_float2(acc[mi][j][2] + b0, acc[mi][j][3] + b1);
        }
    }
}

// ---------------- Kernel C: gate math + group norm + outputs ---------------
__global__ __launch_bounds__(256) void gate_kernel(
    const float* __restrict__ x,      const float* __restrict__ cell,
    const float* __restrict__ normst, const float* __restrict__ maxst,
    const float* __restrict__ gn_w,   const float* __restrict__ gn_b,
    float* __restrict__ dout)
{
    const int blk = blockIdx.x;
    const int b = blk >> 2, n = blk & 3;
    const int tid = threadIdx.x;
    const size_t BH = (size_t)BATCH * HDIM;
    const size_t base = (size_t)b * HDIM + n * HSZ;
    const int c = tid * 4;

    float4 t;
    float iv[4], fv[4], zv[4], ov[4], cv[4], nv[4], mv[4];
    t = *(const float4*)(g_gates + 0 * BH + base + c); iv[0]=t.x; iv[1]=t.y; iv[2]=t.z; iv[3]=t.w;
    t = *(const float4*)(g_gates + 1 * BH + base + c); fv[0]=t.x; fv[1]=t.y; fv[2]=t.z; fv[3]=t.w;
    t = *(const float4*)(g_gates + 2 * BH + base + c); zv[0]=t.x; zv[1]=t.y; zv[2]=t.z; zv[3]=t.w;
    t = *(const float4*)(g_gates + 3 * BH + base + c); ov[0]=t.x; ov[1]=t.y; ov[2]=t.z; ov[3]=t.w;
    t = *(const float4*)(cell   + base + c); cv[0]=t.x; cv[1]=t.y; cv[2]=t.z; cv[3]=t.w;
    t = *(const float4*)(normst + base + c); nv[0]=t.x; nv[1]=t.y; nv[2]=t.z; nv[3]=t.w;
    t = *(const float4*)(maxst  + base + c); mv[0]=t.x; mv[1]=t.y; mv[2]=t.z; mv[3]=t.w;

    float y[4], cn[4], nn[4], mn[4];
    float s = 0.f, sq = 0.f;
#pragma unroll
    for (int j = 0; j < 4; ++j) {
        float fj  = fv[j];
        float lsf = fminf(fj, 0.f) - log1pf(expf(-fabsf(fj)));
        float lfm = mv[j] + lsf;
        float ij  = iv[j];
        float mnew = fmaxf(ij, lfm);
        float ig = expf(ij  - mnew);
        float fg = expf(lfm - mnew);
        float cnew = fg * cv[j] + ig * tanhf(zv[j]);
        float nnew = fg * nv[j] + ig;
        float so   = 1.f / (1.f + expf(-ov[j]));
        float yj   = so * cnew / (nnew + 1e-6f);
        y[j] = yj; cn[j] = cnew; nn[j] = nnew; mn[j] = mnew;
        s += yj; sq += yj * yj;
    }

    __shared__ float rs[8], rq[8];
    float ws = warpSum(s), wq = warpSum(sq);
    if ((tid & 31) == 0) { rs[tid >> 5] = ws; rq[tid >> 5] = wq; }
    __syncthreads();
    float ts = 0.f, tq = 0.f;
#pragma unroll
    for (int i = 0; i < 8; i++) { ts += rs[i]; tq += rq[i]; }
    const float mean = ts * (1.f / HSZ);
    const float var  = tq * (1.f / HSZ) - mean * mean;
    const float rstd = rsqrtf(var + 1e-5f);

    const int h = n * HSZ + c;
    float4 gw = *(const float4*)(gn_w + h);
    float4 gb = *(const float4*)(gn_b + h);
    float4 xs = *(const float4*)(x + base + c);
    const float gwv[4] = { gw.x, gw.y, gw.z, gw.w };
    const float gbv[4] = { gb.x, gb.y, gb.z, gb.w };
    const float xv4[4] = { xs.x, xs.y, xs.z, xs.w };

    float ot[4];
#pragma unroll
    for (int j = 0; j < 4; ++j)
        ot[j] = (y[j] - mean) * rstd * gwv[j] + gbv[j] + xv4[j];

    *(float4*)(dout + 0 * BH + base + c) = make_float4(ot[0], ot[1], ot[2], ot[3]);
    *(float4*)(dout + 4 * BH + base + c) = make_float4(y[0],  y[1],  y[2],  y[3]);
    *(float4*)(dout + 5 * BH + base + c) = make_float4(cn[0], cn[1], cn[2], cn[3]);
    *(float4*)(dout + 6 * BH + base + c) = make_float4(nn[0], nn[1], nn[2], nn[3]);
    *(float4*)(dout + 7 * BH + base + c) = make_float4(mn[0], mn[1], mn[2], mn[3]);
}

// ---------------- launch -----------------------------------------------------
extern "C" void kernel_launch(void* const* d_in, const int* in_sizes, int n_in,
                              void* d_out, int out_size)
{
    const float* x      = (const float*)d_in[0];
    const float* cs     = (const float*)d_in[1];
    const float* rec    = (const float*)d_in[2];
    const float* cell   = (const float*)d_in[3];
    const float* normst = (const float*)d_in[4];
    const float* maxst  = (const float*)d_in[5];
    const float* ln_w   = (const float*)d_in[6];
    const float* conv_w = (const float*)d_in[7];
    const float* conv_b = (const float*)d_in[8];
    const float* wi_in  = (const float*)d_in[9];
    const float* wf_in  = (const float*)d_in[10];
    const float* wz_in  = (const float*)d_in[11];
    const float* wo_in  = (const float*)d_in[12];
    const float* wi_st  = (const float*)d_in[13];
    const float* wf_st  = (const float*)d_in[14];
    const float* wz_st  = (const float*)d_in[15];
    const float* wo_st  = (const float*)d_in[16];
    const float* bi     = (const float*)d_in[17];
    const float* bf_    = (const float*)d_in[18];
    const float* bz     = (const float*)d_in[19];
    const float* bo     = (const float*)d_in[20];
    const float* gn_w   = (const float*)d_in[21];
    const float* gn_b   = (const float*)d_in[22];
    float* out = (float*)d_out;

    static int smem_set = 0;
    if (!smem_set) {
        cudaFuncSetAttribute(gemm_kernel, cudaFuncAttributeMaxDynamicSharedMemorySize,
                             SMEM_B);
        smem_set = 1;
    }

    ln_conv_kernel<<<BATCH, 256>>>(x, cs, ln_w, conv_w, conv_b,
                                   out + (size_t)BATCH * HDIM);

    convert_w_kernel<<<dim3(4096, 8), 256>>>(wi_in, wf_in, wz_in, wo_in,
                                             wi_st, wf_st, wz_st, wo_st);
    convert_rec_kernel<<<8192, 256>>>(rec);

    dim3 grid(HSZ / BN, BATCH / BM, 16);
    gemm_kernel<<<grid, NTHR, SMEM_B>>>(bi, bf_, bz, bo);

    gate_kernel<<<BATCH * NHEAD, 256>>>(x, cell, normst, maxst, gn_w, gn_b, out);
}

// round 9
// speedup vs baseline: 1.3667x; 1.2058x over previous
#include <cuda_runtime.h>
#include <cuda_bf16.h>
#include <math.h>
#include <stdint.h>

#define BATCH 2048
#define HDIM  4096
#define NHEAD 4
#define HSZ   1024

#define BM 128
#define BN 256
#define BK 64              // fp32 elems per K-chunk (256B data rows)
#define NCHUNK 32          // 2 passes * (1024/64)
#define NTHR 256           // 8 warps, 64x64 per warp

#define TSTRIDE 272        // 256B data + 16B pad; 68 words == 4 mod 32 -> conflict-free
#define A_TILE_B (128 * TSTRIDE)
#define B_TILE_B (256 * TSTRIDE)
#define STAGE_B  (A_TILE_B + B_TILE_B)   // 104448
#define SMEM_B   (2 * STAGE_B)           // 208896

#define OFF_A 0
#define OFF_B A_TILE_B

// ---------------- scratch (device globals; no runtime allocation) ----------
__device__ __align__(16) float g_xn   [(size_t)BATCH * HDIM];
__device__ __align__(16) float g_xact [(size_t)BATCH * HDIM];
__device__ __align__(16) float g_rec  [(size_t)BATCH * HDIM];
__device__ __align__(16) float g_w    [8ull * NHEAD * HSZ * HSZ];
__device__ __align__(16) float g_gates[4ull * BATCH * HDIM];

// ---------------- helpers ---------------------------------------------------
__device__ __forceinline__ float warpSum(float v) {
#pragma unroll
    for (int o = 16; o > 0; o >>= 1) v += __shfl_down_sync(0xffffffffu, v, o);
    return v;
}

__device__ __forceinline__ uint32_t smem_u32(const void* p) {
    uint32_t a;
    asm("{ .reg .u64 t; cvta.to.shared.u64 t, %1; cvt.u32.u64 %0, t; }"
        : "=r"(a) : "l"(p));
    return a;
}

__device__ __forceinline__ void cp16(uint32_t saddr, const void* gaddr) {
    asm volatile("cp.async.cg.shared.global [%0], [%1], 16;"
                 :: "r"(saddr), "l"(gaddr));
}

__device__ __forceinline__ float tf32r(float x) {
    uint32_t u;
    asm("cvt.rna.tf32.f32 %0, %1;" : "=r"(u) : "f"(x));
    return __uint_as_float(u);
}

__device__ __forceinline__ void mma_tf32(float* c, uint32_t a0, uint32_t a1,
                                         uint32_t a2, uint32_t a3,
                                         uint32_t b0, uint32_t b1) {
    asm volatile(
        "mma.sync.aligned.m16n8k8.row.col.f32.tf32.tf32.f32 "
        "{%0,%1,%2,%3}, {%4,%5,%6,%7}, {%8,%9}, {%0,%1,%2,%3};"
        : "+f"(c[0]), "+f"(c[1]), "+f"(c[2]), "+f"(c[3])
        : "r"(a0), "r"(a1), "r"(a2), "r"(a3), "r"(b0), "r"(b1));
}

__device__ __forceinline__ uint32_t lds32(uint32_t a) {
    uint32_t v;
    asm volatile("ld.shared.b32 %0, [%1];" : "=r"(v) : "r"(a));
    return v;
}

// ---------------- Kernel A: layernorm + conv + silu + tf32 emit ------------
__global__ __launch_bounds__(256) void ln_conv_kernel(
    const float* __restrict__ x, const float* __restrict__ cs,
    const float* __restrict__ ln_w, const float* __restrict__ conv_w,
    const float* __restrict__ conv_b, float* __restrict__ out_ncs)
{
    const int b   = blockIdx.x;
    const int tid = threadIdx.x;
    const float* xr = x + (size_t)b * HDIM;

    float4 xv[4];
    float s = 0.f, sq = 0.f;
#pragma unroll
    for (int i = 0; i < 4; i++) {
        xv[i] = *(const float4*)(xr + (size_t)(tid + i * 256) * 4);
        s  += xv[i].x + xv[i].y + xv[i].z + xv[i].w;
        sq += xv[i].x * xv[i].x + xv[i].y * xv[i].y + xv[i].z * xv[i].z + xv[i].w * xv[i].w;
    }
    __shared__ float rs[8], rq[8];
    float ws = warpSum(s), wq = warpSum(sq);
    if ((tid & 31) == 0) { rs[tid >> 5] = ws; rq[tid >> 5] = wq; }
    __syncthreads();
    float ts = 0.f, tq = 0.f;
#pragma unroll
    for (int i = 0; i < 8; i++) { ts += rs[i]; tq += rq[i]; }
    const float mean = ts * (1.f / HDIM);
    const float var  = tq * (1.f / HDIM) - mean * mean;
    const float rstd = rsqrtf(var + 1e-5f);

    const float* csb = cs      + (size_t)b * 3 * HDIM;
    float*       ncs = out_ncs + (size_t)b * 3 * HDIM;

#pragma unroll
    for (int i = 0; i < 4; i++) {
        const int c = (tid + i * 256) * 4;
        float4 lw = *(const float4*)(ln_w + c);
        float4 xn;
        xn.x = (xv[i].x - mean) * rstd * lw.x;
        xn.y = (xv[i].y - mean) * rstd * lw.y;
        xn.z = (xv[i].z - mean) * rstd * lw.z;
        xn.w = (xv[i].w - mean) * rstd * lw.w;

        float4 c0 = *(const float4*)(csb + c);
        float4 c1 = *(const float4*)(csb + HDIM + c);
        float4 c2 = *(const float4*)(csb + 2 * HDIM + c);
        float4 cb = *(const float4*)(conv_b + c);
        float4 w0 = *(const float4*)(conv_w + (size_t)(c + 0) * 4);
        float4 w1 = *(const float4*)(conv_w + (size_t)(c + 1) * 4);
        float4 w2 = *(const float4*)(conv_w + (size_t)(c + 2) * 4);
        float4 w3 = *(const float4*)(conv_w + (size_t)(c + 3) * 4);

        float4 xc;
        xc.x = c0.x * w0.x + c1.x * w0.y + c2.x * w0.z + xn.x * w0.w + cb.x;
        xc.y = c0.y * w1.x + c1.y * w1.y + c2.y * w1.z + xn.y * w1.w + cb.y;
        xc.z = c0.z * w2.x + c1.z * w2.y + c2.z * w2.z + xn.z * w2.w + cb.z;
        xc.w = c0.w * w3.x + c1.w * w3.y + c2.w * w3.z + xn.w * w3.w + cb.w;

        float4 xa;
        xa.x = xc.x / (1.f + expf(-xc.x));
        xa.y = xc.y / (1.f + expf(-xc.y));
        xa.z = xc.z / (1.f + expf(-xc.z));
        xa.w = xc.w / (1.f + expf(-xc.w));

        float4 xnr, xar;
        xnr.x = tf32r(xn.x); xnr.y = tf32r(xn.y); xnr.z = tf32r(xn.z); xnr.w = tf32r(xn.w);
        xar.x = tf32r(xa.x); xar.y = tf32r(xa.y); xar.z = tf32r(xa.z); xar.w = tf32r(xa.w);

        const size_t off = (size_t)b * HDIM + c;
        *(float4*)(g_xn   + off) = xnr;
        *(float4*)(g_xact + off) = xar;

        *(float4*)(ncs + c)            = c1;
        *(float4*)(ncs + HDIM + c)     = c2;
        *(float4*)(ncs + 2 * HDIM + c) = xn;
    }
}

// ---------------- conversion kernels ----------------------------------------
__global__ __launch_bounds__(256) void convert_w_kernel(
    const float* __restrict__ w0, const float* __restrict__ w1,
    const float* __restrict__ w2, const float* __restrict__ w3,
    const float* __restrict__ w4, const float* __restrict__ w5,
    const float* __restrict__ w6, const float* __restrict__ w7)
{
    const float* srcs[8] = { w0, w1, w2, w3, w4, w5, w6, w7 };
    const float* s = srcs[blockIdx.y];
    const size_t base4 = (size_t)blockIdx.y * (NHEAD * HSZ * (HSZ / 4));
    const int i = blockIdx.x * 256 + threadIdx.x;
    float4 v = ((const float4*)s)[i];
    float4 r;
    r.x = tf32r(v.x); r.y = tf32r(v.y); r.z = tf32r(v.z); r.w = tf32r(v.w);
    ((float4*)g_w)[base4 + i] = r;
}

__global__ __launch_bounds__(256) void convert_rec_kernel(const float* __restrict__ src)
{
    const int i = blockIdx.x * 256 + threadIdx.x;
    float4 v = ((const float4*)src)[i];
    float4 r;
    r.x = tf32r(v.x); r.y = tf32r(v.y); r.z = tf32r(v.z); r.w = tf32r(v.w);
    ((float4*)g_rec)[i] = r;
}

// ---------------- Kernel B: TF32 single-pass GEMM (8 warps, 64x64/warp) ----
__global__ __launch_bounds__(NTHR, 1) void gemm_kernel(
    const float* __restrict__ bi, const float* __restrict__ bf_,
    const float* __restrict__ bz, const float* __restrict__ bo)
{
    extern __shared__ __align__(1024) char smem[];
    const uint32_t sbase = smem_u32(smem);
    const int tid  = threadIdx.x;
    const int wid  = tid >> 5;
    const int lane = tid & 31;

    const int g  = blockIdx.z >> 2;
    const int nh = blockIdx.z & 3;
    const int m0 = blockIdx.y * BM;
    const int n0 = blockIdx.x * BN;

    const float* aSrc0 = (g < 2 ? g_xact : g_xn);
    const size_t wb0 = ((size_t)g)       * NHEAD * HSZ * HSZ + (size_t)nh * HSZ * HSZ;
    const size_t wb1 = ((size_t)(g + 4)) * NHEAD * HSZ * HSZ + (size_t)nh * HSZ * HSZ;

    // loader: 24 cp16 per thread per chunk (A: 8 iters, B: 16 iters)
    auto load_chunk = [&](int c) {
        const int pass = c >> 4;
        const int kt   = (c & 15) * BK;
        const uint32_t st = sbase + (uint32_t)(c & 1) * STAGE_B;
        const float* A = (pass ? g_rec : aSrc0);
        const float* W = g_w + (pass ? wb1 : wb0);
#pragma unroll
        for (int t = 0; t < 8; t++) {
            const int idx = tid + t * NTHR;         // 0..2047
            const int row = idx >> 4;               // 0..127
            const int sec = idx & 15;
            const uint32_t sdst = st + OFF_A + (uint32_t)row * TSTRIDE + sec * 16;
            cp16(sdst, A + (size_t)(m0 + row) * HDIM + (size_t)nh * HSZ + kt + sec * 4);
        }
#pragma unroll
        for (int t = 0; t < 16; t++) {
            const int idx = tid + t * NTHR;         // 0..4095
            const int row = idx >> 4;               // 0..255
            const int sec = idx & 15;
            const uint32_t sdst = st + OFF_B + (uint32_t)row * TSTRIDE + sec * 16;
            cp16(sdst, W + (size_t)(n0 + row) * HSZ + kt + sec * 4);
        }
        asm volatile("cp.async.commit_group;");
    };

    // warp tiling: 2 warps along M (64 rows), 4 along N (64 cols)
    const int wm = wid & 1;
    const int wn = wid >> 1;
    const int grp = lane >> 2;      // 0..7
    const int thr = lane & 3;       // 0..3

    // fragment base addresses (within stage)
    const uint32_t aBase = OFF_A + (uint32_t)(wm * 64 + grp) * TSTRIDE + thr * 4;
    const uint32_t bBase = OFF_B + (uint32_t)(wn * 64 + grp) * TSTRIDE + thr * 4;

    float acc[4][8][4];
#pragma unroll
    for (int mi = 0; mi < 4; mi++)
#pragma unroll
        for (int j = 0; j < 8; j++)
#pragma unroll
            for (int q = 0; q < 4; q++) acc[mi][j][q] = 0.f;

    load_chunk(0);

#pragma unroll 1
    for (int c = 0; c < NCHUNK; c++) {
        asm volatile("cp.async.wait_group 0;");   // chunk c landed
        __syncthreads();                          // all warps done computing c-1
        if (c + 1 < NCHUNK) load_chunk(c + 1);    // into other stage, safe now

        const uint32_t st = sbase + (uint32_t)(c & 1) * STAGE_B;
#pragma unroll
        for (int kk = 0; kk < 8; kk++) {          // 8 k-steps of 8
            const uint32_t ka = st + aBase + kk * 32;
            const uint32_t kb = st + bBase + kk * 32;

            uint32_t a0[4], a1[4], a2[4], a3[4];
#pragma unroll
            for (int mi = 0; mi < 4; mi++) {
                const uint32_t r = ka + (uint32_t)(mi * 16) * TSTRIDE;
                a0[mi] = lds32(r);
                a1[mi] = lds32(r + 8 * TSTRIDE);
                a2[mi] = lds32(r + 16);
                a3[mi] = lds32(r + 8 * TSTRIDE + 16);
            }
            uint32_t b0[8], b1[8];
#pragma unroll
            for (int jj = 0; jj < 8; jj++) {
                const uint32_t r = kb + (uint32_t)(jj * 8) * TSTRIDE;
                b0[jj] = lds32(r);
                b1[jj] = lds32(r + 16);
            }
#pragma unroll
            for (int jj = 0; jj < 8; jj++)
#pragma unroll
                for (int mi = 0; mi < 4; mi++)
                    mma_tf32(acc[mi][jj], a0[mi], a1[mi], a2[mi], a3[mi],
                             b0[jj], b1[jj]);
        }
    }

    // epilogue: add bias, write gates
    const float* bias = (g == 0) ? bi : (g == 1) ? bf_ : (g == 2) ? bz : bo;
    float* gbase = g_gates + (size_t)g * BATCH * HDIM;

#pragma unroll
    for (int mi = 0; mi < 4; mi++) {
        const int row0 = m0 + wm * 64 + mi * 16 + grp;
#pragma unroll
        for (int j = 0; j < 8; j++) {
            const int col = n0 + wn * 64 + j * 8 + thr * 2;
            const int h   = nh * HSZ + col;
            const float b0v = bias[h], b1v = bias[h + 1];
            float* p0 = gbase + (size_t)row0 * HDIM + h;
            float* p1 = p0 + 8 * HDIM;
            *(float2*)p0 = make_float2(acc[mi][j][0] + b0v, acc[mi][j][1] + b1v);
            *(float2*)p1 = make_float2(acc[mi][j][2] + b0v, acc[mi][j][3] + b1v);
        }
    }
}

// ---------------- Kernel C: gate math + group norm + outputs ---------------
__global__ __launch_bounds__(256) void gate_kernel(
    const float* __restrict__ x,      const float* __restrict__ cell,
    const float* __restrict__ normst, const float* __restrict__ maxst,
    const float* __restrict__ gn_w,   const float* __restrict__ gn_b,
    float* __restrict__ dout)
{
    const int blk = blockIdx.x;
    const int b = blk >> 2, n = blk & 3;
    const int tid = threadIdx.x;
    const size_t BH = (size_t)BATCH * HDIM;
    const size_t base = (size_t)b * HDIM + n * HSZ;
    const int c = tid * 4;

    float4 t;
    float iv[4], fv[4], zv[4], ov[4], cv[4], nv[4], mv[4];
    t = *(const float4*)(g_gates + 0 * BH + base + c); iv[0]=t.x; iv[1]=t.y; iv[2]=t.z; iv[3]=t.w;
    t = *(const float4*)(g_gates + 1 * BH + base + c); fv[0]=t.x; fv[1]=t.y; fv[2]=t.z; fv[3]=t.w;
    t = *(const float4*)(g_gates + 2 * BH + base + c); zv[0]=t.x; zv[1]=t.y; zv[2]=t.z; zv[3]=t.w;
    t = *(const float4*)(g_gates + 3 * BH + base + c); ov[0]=t.x; ov[1]=t.y; ov[2]=t.z; ov[3]=t.w;
    t = *(const float4*)(cell   + base + c); cv[0]=t.x; cv[1]=t.y; cv[2]=t.z; cv[3]=t.w;
    t = *(const float4*)(normst + base + c); nv[0]=t.x; nv[1]=t.y; nv[2]=t.z; nv[3]=t.w;
    t = *(const float4*)(maxst  + base + c); mv[0]=t.x; mv[1]=t.y; mv[2]=t.z; mv[3]=t.w;

    float y[4], cn[4], nn[4], mn[4];
    float s = 0.f, sq = 0.f;
#pragma unroll
    for (int j = 0; j < 4; ++j) {
        float fj  = fv[j];
        float lsf = fminf(fj, 0.f) - log1pf(expf(-fabsf(fj)));
        float lfm = mv[j] + lsf;
        float ij  = iv[j];
        float mnew = fmaxf(ij, lfm);
        float ig = expf(ij  - mnew);
        float fg = expf(lfm - mnew);
        float cnew = fg * cv[j] + ig * tanhf(zv[j]);
        float nnew = fg * nv[j] + ig;
        float so   = 1.f / (1.f + expf(-ov[j]));
        float yj   = so * cnew / (nnew + 1e-6f);
        y[j] = yj; cn[j] = cnew; nn[j] = nnew; mn[j] = mnew;
        s += yj; sq += yj * yj;
    }

    __shared__ float rs[8], rq[8];
    float ws = warpSum(s), wq = warpSum(sq);
    if ((tid & 31) == 0) { rs[tid >> 5] = ws; rq[tid >> 5] = wq; }
    __syncthreads();
    float ts = 0.f, tq = 0.f;
#pragma unroll
    for (int i = 0; i < 8; i++) { ts += rs[i]; tq += rq[i]; }
    const float mean = ts * (1.f / HSZ);
    const float var  = tq * (1.f / HSZ) - mean * mean;
    const float rstd = rsqrtf(var + 1e-5f);

    const int h = n * HSZ + c;
    float4 gw = *(const float4*)(gn_w + h);
    float4 gb = *(const float4*)(gn_b + h);
    float4 xs = *(const float4*)(x + base + c);
    const float gwv[4] = { gw.x, gw.y, gw.z, gw.w };
    const float gbv[4] = { gb.x, gb.y, gb.z, gb.w };
    const float xv4[4] = { xs.x, xs.y, xs.z, xs.w };

    float ot[4];
#pragma unroll
    for (int j = 0; j < 4; ++j)
        ot[j] = (y[j] - mean) * rstd * gwv[j] + gbv[j] + xv4[j];

    *(float4*)(dout + 0 * BH + base + c) = make_float4(ot[0], ot[1], ot[2], ot[3]);
    *(float4*)(dout + 4 * BH + base + c) = make_float4(y[0],  y[1],  y[2],  y[3]);
    *(float4*)(dout + 5 * BH + base + c) = make_float4(cn[0], cn[1], cn[2], cn[3]);
    *(float4*)(dout + 6 * BH + base + c) = make_float4(nn[0], nn[1], nn[2], nn[3]);
    *(float4*)(dout + 7 * BH + base + c) = make_float4(mn[0], mn[1], mn[2], mn[3]);
}

// ---------------- launch -----------------------------------------------------
extern "C" void kernel_launch(void* const* d_in, const int* in_sizes, int n_in,
                              void* d_out, int out_size)
{
    const float* x      = (const float*)d_in[0];
    const float* cs     = (const float*)d_in[1];
    const float* rec    = (const float*)d_in[2];
    const float* cell   = (const float*)d_in[3];
    const float* normst = (const float*)d_in[4];
    const float* maxst  = (const float*)d_in[5];
    const float* ln_w   = (const float*)d_in[6];
    const float* conv_w = (const float*)d_in[7];
    const float* conv_b = (const float*)d_in[8];
    const float* wi_in  = (const float*)d_in[9];
    const float* wf_in  = (const float*)d_in[10];
    const float* wz_in  = (const float*)d_in[11];
    const float* wo_in  = (const float*)d_in[12];
    const float* wi_st  = (const float*)d_in[13];
    const float* wf_st  = (const float*)d_in[14];
    const float* wz_st  = (const float*)d_in[15];
    const float* wo_st  = (const float*)d_in[16];
    const float* bi     = (const float*)d_in[17];
    const float* bf_    = (const float*)d_in[18];
    const float* bz     = (const float*)d_in[19];
    const float* bo     = (const float*)d_in[20];
    const float* gn_w   = (const float*)d_in[21];
    const float* gn_b   = (const float*)d_in[22];
    float* out = (float*)d_out;

    static int smem_set = 0;
    if (!smem_set) {
        cudaFuncSetAttribute(gemm_kernel, cudaFuncAttributeMaxDynamicSharedMemorySize,
                             SMEM_B);
        smem_set = 1;
    }

    ln_conv_kernel<<<BATCH, 256>>>(x, cs, ln_w, conv_w, conv_b,
                                   out + (size_t)BATCH * HDIM);

    convert_w_kernel<<<dim3(4096, 8), 256>>>(wi_in, wf_in, wz_in, wo_in,
                                             wi_st, wf_st, wz_st, wo_st);
    convert_rec_kernel<<<8192, 256>>>(rec);

    dim3 grid(HSZ / BN, BATCH / BM, 16);
    gemm_kernel<<<grid, NTHR, SMEM_B>>>(bi, bf_, bz, bo);

    gate_kernel<<<BATCH * NHEAD, 256>>>(x, cell, normst, maxst, gn_w, gn_b, out);
}

// round 10
// speedup vs baseline: 1.3921x; 1.0186x over previous
#include <cuda_runtime.h>
#include <cuda_bf16.h>
#include <math.h>
#include <stdint.h>

#define BATCH 2048
#define HDIM  4096
#define NHEAD 4
#define HSZ   1024

#define BM 128
#define BN 256
#define BK 64              // fp32 elems per K-chunk (256B data rows)
#define NCHUNK 32          // 2 passes * (1024/64)
#define NTHR 256           // 8 warps, 64x64 per warp

#define TSTRIDE 272        // 256B data + 16B pad; 68 words == 4 mod 32 -> LDSM conflict-free
#define A_TILE_B (128 * TSTRIDE)
#define B_TILE_B (256 * TSTRIDE)
#define STAGE_B  (A_TILE_B + B_TILE_B)   // 104448
#define SMEM_B   (2 * STAGE_B)           // 208896

#define OFF_A 0
#define OFF_B A_TILE_B

// ---------------- scratch (device globals; no runtime allocation) ----------
__device__ __align__(16) float g_xn   [(size_t)BATCH * HDIM];
__device__ __align__(16) float g_xact [(size_t)BATCH * HDIM];
__device__ __align__(16) float g_rec  [(size_t)BATCH * HDIM];
__device__ __align__(16) float g_w    [8ull * NHEAD * HSZ * HSZ];
__device__ __align__(16) float g_gates[4ull * BATCH * HDIM];

// ---------------- helpers ---------------------------------------------------
__device__ __forceinline__ float warpSum(float v) {
#pragma unroll
    for (int o = 16; o > 0; o >>= 1) v += __shfl_down_sync(0xffffffffu, v, o);
    return v;
}

__device__ __forceinline__ uint32_t smem_u32(const void* p) {
    uint32_t a;
    asm("{ .reg .u64 t; cvta.to.shared.u64 t, %1; cvt.u32.u64 %0, t; }"
        : "=r"(a) : "l"(p));
    return a;
}

__device__ __forceinline__ void cp16(uint32_t saddr, const void* gaddr) {
    asm volatile("cp.async.cg.shared.global [%0], [%1], 16;"
                 :: "r"(saddr), "l"(gaddr));
}

__device__ __forceinline__ float tf32r(float x) {
    uint32_t u;
    asm("cvt.rna.tf32.f32 %0, %1;" : "=r"(u) : "f"(x));
    return __uint_as_float(u);
}

__device__ __forceinline__ void ldsm4(uint32_t* r, uint32_t a) {
    asm volatile("ldmatrix.sync.aligned.m8n8.x4.shared.b16 {%0,%1,%2,%3}, [%4];"
                 : "=r"(r[0]), "=r"(r[1]), "=r"(r[2]), "=r"(r[3]) : "r"(a));
}

__device__ __forceinline__ void mma_tf32(float* c, uint32_t a0, uint32_t a1,
                                         uint32_t a2, uint32_t a3,
                                         uint32_t b0, uint32_t b1) {
    asm volatile(
        "mma.sync.aligned.m16n8k8.row.col.f32.tf32.tf32.f32 "
        "{%0,%1,%2,%3}, {%4,%5,%6,%7}, {%8,%9}, {%0,%1,%2,%3};"
        : "+f"(c[0]), "+f"(c[1]), "+f"(c[2]), "+f"(c[3])
        : "r"(a0), "r"(a1), "r"(a2), "r"(a3), "r"(b0), "r"(b1));
}

// ---------------- Kernel A: layernorm + conv + silu + tf32 emit ------------
__global__ __launch_bounds__(256) void ln_conv_kernel(
    const float* __restrict__ x, const float* __restrict__ cs,
    const float* __restrict__ ln_w, const float* __restrict__ conv_w,
    const float* __restrict__ conv_b, float* __restrict__ out_ncs)
{
    const int b   = blockIdx.x;
    const int tid = threadIdx.x;
    const float* xr = x + (size_t)b * HDIM;

    float4 xv[4];
    float s = 0.f, sq = 0.f;
#pragma unroll
    for (int i = 0; i < 4; i++) {
        xv[i] = *(const float4*)(xr + (size_t)(tid + i * 256) * 4);
        s  += xv[i].x + xv[i].y + xv[i].z + xv[i].w;
        sq += xv[i].x * xv[i].x + xv[i].y * xv[i].y + xv[i].z * xv[i].z + xv[i].w * xv[i].w;
    }
    __shared__ float rs[8], rq[8];
    float ws = warpSum(s), wq = warpSum(sq);
    if ((tid & 31) == 0) { rs[tid >> 5] = ws; rq[tid >> 5] = wq; }
    __syncthreads();
    float ts = 0.f, tq = 0.f;
#pragma unroll
    for (int i = 0; i < 8; i++) { ts += rs[i]; tq += rq[i]; }
    const float mean = ts * (1.f / HDIM);
    const float var  = tq * (1.f / HDIM) - mean * mean;
    const float rstd = rsqrtf(var + 1e-5f);

    const float* csb = cs      + (size_t)b * 3 * HDIM;
    float*       ncs = out_ncs + (size_t)b * 3 * HDIM;

#pragma unroll
    for (int i = 0; i < 4; i++) {
        const int c = (tid + i * 256) * 4;
        float4 lw = *(const float4*)(ln_w + c);
        float4 xn;
        xn.x = (xv[i].x - mean) * rstd * lw.x;
        xn.y = (xv[i].y - mean) * rstd * lw.y;
        xn.z = (xv[i].z - mean) * rstd * lw.z;
        xn.w = (xv[i].w - mean) * rstd * lw.w;

        float4 c0 = *(const float4*)(csb + c);
        float4 c1 = *(const float4*)(csb + HDIM + c);
        float4 c2 = *(const float4*)(csb + 2 * HDIM + c);
        float4 cb = *(const float4*)(conv_b + c);
        float4 w0 = *(const float4*)(conv_w + (size_t)(c + 0) * 4);
        float4 w1 = *(const float4*)(conv_w + (size_t)(c + 1) * 4);
        float4 w2 = *(const float4*)(conv_w + (size_t)(c + 2) * 4);
        float4 w3 = *(const float4*)(conv_w + (size_t)(c + 3) * 4);

        float4 xc;
        xc.x = c0.x * w0.x + c1.x * w0.y + c2.x * w0.z + xn.x * w0.w + cb.x;
        xc.y = c0.y * w1.x + c1.y * w1.y + c2.y * w1.z + xn.y * w1.w + cb.y;
        xc.z = c0.z * w2.x + c1.z * w2.y + c2.z * w2.z + xn.z * w2.w + cb.z;
        xc.w = c0.w * w3.x + c1.w * w3.y + c2.w * w3.z + xn.w * w3.w + cb.w;

        float4 xa;
        xa.x = xc.x / (1.f + expf(-xc.x));
        xa.y = xc.y / (1.f + expf(-xc.y));
        xa.z = xc.z / (1.f + expf(-xc.z));
        xa.w = xc.w / (1.f + expf(-xc.w));

        float4 xnr, xar;
        xnr.x = tf32r(xn.x); xnr.y = tf32r(xn.y); xnr.z = tf32r(xn.z); xnr.w = tf32r(xn.w);
        xar.x = tf32r(xa.x); xar.y = tf32r(xa.y); xar.z = tf32r(xa.z); xar.w = tf32r(xa.w);

        const size_t off = (size_t)b * HDIM + c;
        *(float4*)(g_xn   + off) = xnr;
        *(float4*)(g_xact + off) = xar;

        *(float4*)(ncs + c)            = c1;
        *(float4*)(ncs + HDIM + c)     = c2;
        *(float4*)(ncs + 2 * HDIM + c) = xn;
    }
}

// ---------------- conversion kernels ----------------------------------------
__global__ __launch_bounds__(256) void convert_w_kernel(
    const float* __restrict__ w0, const float* __restrict__ w1,
    const float* __restrict__ w2, const float* __restrict__ w3,
    const float* __restrict__ w4, const float* __restrict__ w5,
    const float* __restrict__ w6, const float* __restrict__ w7)
{
    const float* srcs[8] = { w0, w1, w2, w3, w4, w5, w6, w7 };
    const float* s = srcs[blockIdx.y];
    const size_t base4 = (size_t)blockIdx.y * (NHEAD * HSZ * (HSZ / 4));
    const int i = blockIdx.x * 256 + threadIdx.x;
    float4 v = ((const float4*)s)[i];
    float4 r;
    r.x = tf32r(v.x); r.y = tf32r(v.y); r.z = tf32r(v.z); r.w = tf32r(v.w);
    ((float4*)g_w)[base4 + i] = r;
}

__global__ __launch_bounds__(256) void convert_rec_kernel(const float* __restrict__ src)
{
    const int i = blockIdx.x * 256 + threadIdx.x;
    float4 v = ((const float4*)src)[i];
    float4 r;
    r.x = tf32r(v.x); r.y = tf32r(v.y); r.z = tf32r(v.z); r.w = tf32r(v.w);
    ((float4*)g_rec)[i] = r;
}

// ---------------- Kernel B: TF32 GEMM, ldmatrix fragment loads -------------
__global__ __launch_bounds__(NTHR, 1) void gemm_kernel(
    const float* __restrict__ bi, const float* __restrict__ bf_,
    const float* __restrict__ bz, const float* __restrict__ bo)
{
    extern __shared__ __align__(1024) char smem[];
    const uint32_t sbase = smem_u32(smem);
    const int tid  = threadIdx.x;
    const int wid  = tid >> 5;
    const int lane = tid & 31;

    const int g  = blockIdx.z >> 2;
    const int nh = blockIdx.z & 3;
    const int m0 = blockIdx.y * BM;
    const int n0 = blockIdx.x * BN;

    const float* aSrc0 = (g < 2 ? g_xact : g_xn);
    const size_t wb0 = ((size_t)g)       * NHEAD * HSZ * HSZ + (size_t)nh * HSZ * HSZ;
    const size_t wb1 = ((size_t)(g + 4)) * NHEAD * HSZ * HSZ + (size_t)nh * HSZ * HSZ;

    // loader: 24 cp16 per thread per chunk (A: 8 iters, B: 16 iters)
    auto load_chunk = [&](int c) {
        const int pass = c >> 4;
        const int kt   = (c & 15) * BK;
        const uint32_t st = sbase + (uint32_t)(c & 1) * STAGE_B;
        const float* A = (pass ? g_rec : aSrc0);
        const float* W = g_w + (pass ? wb1 : wb0);
#pragma unroll
        for (int t = 0; t < 8; t++) {
            const int idx = tid + t * NTHR;         // 0..2047
            const int row = idx >> 4;               // 0..127
            const int sec = idx & 15;
            const uint32_t sdst = st + OFF_A + (uint32_t)row * TSTRIDE + sec * 16;
            cp16(sdst, A + (size_t)(m0 + row) * HDIM + (size_t)nh * HSZ + kt + sec * 4);
        }
#pragma unroll
        for (int t = 0; t < 16; t++) {
            const int idx = tid + t * NTHR;         // 0..4095
            const int row = idx >> 4;               // 0..255
            const int sec = idx & 15;
            const uint32_t sdst = st + OFF_B + (uint32_t)row * TSTRIDE + sec * 16;
            cp16(sdst, W + (size_t)(n0 + row) * HSZ + kt + sec * 4);
        }
        asm volatile("cp.async.commit_group;");
    };

    // warp tiling: 2 warps along M (64 rows), 4 along N (64 cols)
    const int wm = wid & 1;
    const int wn = wid >> 1;
    const int grp = lane >> 2;      // 0..7
    const int thr = lane & 3;       // 0..3

    // ldmatrix per-lane base addresses (within stage)
    // A tiles (per mi): t0=rows0-7/k0-3, t1=rows8-15/k0-3, t2=rows0-7/k4-7, t3=rows8-15/k4-7
    const uint32_t aLdsmBase = OFF_A
        + (uint32_t)(wm * 64 + (lane & 15)) * TSTRIDE
        + (uint32_t)(lane >> 4) * 16;
    // B tiles (per jj-pair jp): t0=b0[2jp], t1=b1[2jp], t2=b0[2jp+1], t3=b1[2jp+1]
    const uint32_t bLdsmBase = OFF_B
        + (uint32_t)(wn * 64 + (lane & 7) + (lane >> 4) * 8) * TSTRIDE
        + (uint32_t)((lane >> 3) & 1) * 16;

    float acc[4][8][4];
#pragma unroll
    for (int mi = 0; mi < 4; mi++)
#pragma unroll
        for (int j = 0; j < 8; j++)
#pragma unroll
            for (int q = 0; q < 4; q++) acc[mi][j][q] = 0.f;

    load_chunk(0);

#pragma unroll 1
    for (int c = 0; c < NCHUNK; c++) {
        asm volatile("cp.async.wait_group 0;");   // chunk c landed
        __syncthreads();                          // all warps done computing c-1
        if (c + 1 < NCHUNK) load_chunk(c + 1);    // into other stage, safe now

        const uint32_t st = sbase + (uint32_t)(c & 1) * STAGE_B;
#pragma unroll
        for (int kk = 0; kk < 8; kk++) {          // 8 k-steps of 8
            const uint32_t ka = st + aLdsmBase + kk * 32;
            const uint32_t kb = st + bLdsmBase + kk * 32;

            uint32_t af[4][4];                    // [mi][a0..a3]
#pragma unroll
            for (int mi = 0; mi < 4; mi++)
                ldsm4(af[mi], ka + (uint32_t)(mi * 16) * TSTRIDE);

            uint32_t bf[4][4];                    // [jp][b0,b1,b0',b1']
#pragma unroll
            for (int jp = 0; jp < 4; jp++)
                ldsm4(bf[jp], kb + (uint32_t)(jp * 16) * TSTRIDE);

#pragma unroll
            for (int jp = 0; jp < 4; jp++)
#pragma unroll
                for (int mi = 0; mi < 4; mi++) {
                    mma_tf32(acc[mi][2 * jp],     af[mi][0], af[mi][1], af[mi][2], af[mi][3],
                             bf[jp][0], bf[jp][1]);
                    mma_tf32(acc[mi][2 * jp + 1], af[mi][0], af[mi][1], af[mi][2], af[mi][3],
                             bf[jp][2], bf[jp][3]);
                }
        }
    }

    // epilogue: add bias, write gates
    const float* bias = (g == 0) ? bi : (g == 1) ? bf_ : (g == 2) ? bz : bo;
    float* gbase = g_gates + (size_t)g * BATCH * HDIM;

#pragma unroll
    for (int mi = 0; mi < 4; mi++) {
        const int row0 = m0 + wm * 64 + mi * 16 + grp;
#pragma unroll
        for (int j = 0; j < 8; j++) {
            const int col = n0 + wn * 64 + j * 8 + thr * 2;
            const int h   = nh * HSZ + col;
            const float b0v = bias[h], b1v = bias[h + 1];
            float* p0 = gbase + (size_t)row0 * HDIM + h;
            float* p1 = p0 + 8 * HDIM;
            *(float2*)p0 = make_float2(acc[mi][j][0] + b0v, acc[mi][j][1] + b1v);
            *(float2*)p1 = make_float2(acc[mi][j][2] + b0v, acc[mi][j][3] + b1v);
        }
    }
}

// ---------------- Kernel C: gate math + group norm + outputs ---------------
__global__ __launch_bounds__(256) void gate_kernel(
    const float* __restrict__ x,      const float* __restrict__ cell,
    const float* __restrict__ normst, const float* __restrict__ maxst,
    const float* __restrict__ gn_w,   const float* __restrict__ gn_b,
    float* __restrict__ dout)
{
    const int blk = blockIdx.x;
    const int b = blk >> 2, n = blk & 3;
    const int tid = threadIdx.x;
    const size_t BH = (size_t)BATCH * HDIM;
    const size_t base = (size_t)b * HDIM + n * HSZ;
    const int c = tid * 4;

    float4 t;
    float iv[4], fv[4], zv[4], ov[4], cv[4], nv[4], mv[4];
    t = *(const float4*)(g_gates + 0 * BH + base + c); iv[0]=t.x; iv[1]=t.y; iv[2]=t.z; iv[3]=t.w;
    t = *(const float4*)(g_gates + 1 * BH + base + c); fv[0]=t.x; fv[1]=t.y; fv[2]=t.z; fv[3]=t.w;
    t = *(const float4*)(g_gates + 2 * BH + base + c); zv[0]=t.x; zv[1]=t.y; zv[2]=t.z; zv[3]=t.w;
    t = *(const float4*)(g_gates + 3 * BH + base + c); ov[0]=t.x; ov[1]=t.y; ov[2]=t.z; ov[3]=t.w;
    t = *(const float4*)(cell   + base + c); cv[0]=t.x; cv[1]=t.y; cv[2]=t.z; cv[3]=t.w;
    t = *(const float4*)(normst + base + c); nv[0]=t.x; nv[1]=t.y; nv[2]=t.z; nv[3]=t.w;
    t = *(const float4*)(maxst  + base + c); mv[0]=t.x; mv[1]=t.y; mv[2]=t.z; mv[3]=t.w;

    float y[4], cn[4], nn[4], mn[4];
    float s = 0.f, sq = 0.f;
#pragma unroll
    for (int j = 0; j < 4; ++j) {
        float fj  = fv[j];
        float lsf = fminf(fj, 0.f) - log1pf(expf(-fabsf(fj)));
        float lfm = mv[j] + lsf;
        float ij  = iv[j];
        float mnew = fmaxf(ij, lfm);
        float ig = expf(ij  - mnew);
        float fg = expf(lfm - mnew);
        float cnew = fg * cv[j] + ig * tanhf(zv[j]);
        float nnew = fg * nv[j] + ig;
        float so   = 1.f / (1.f + expf(-ov[j]));
        float yj   = so * cnew / (nnew + 1e-6f);
        y[j] = yj; cn[j] = cnew; nn[j] = nnew; mn[j] = mnew;
        s += yj; sq += yj * yj;
    }

    __shared__ float rs[8], rq[8];
    float ws = warpSum(s), wq = warpSum(sq);
    if ((tid & 31) == 0) { rs[tid >> 5] = ws; rq[tid >> 5] = wq; }
    __syncthreads();
    float ts = 0.f, tq = 0.f;
#pragma unroll
    for (int i = 0; i < 8; i++) { ts += rs[i]; tq += rq[i]; }
    const float mean = ts * (1.f / HSZ);
    const float var  = tq * (1.f / HSZ) - mean * mean;
    const float rstd = rsqrtf(var + 1e-5f);

    const int h = n * HSZ + c;
    float4 gw = *(const float4*)(gn_w + h);
    float4 gb = *(const float4*)(gn_b + h);
    float4 xs = *(const float4*)(x + base + c);
    const float gwv[4] = { gw.x, gw.y, gw.z, gw.w };
    const float gbv[4] = { gb.x, gb.y, gb.z, gb.w };
    const float xv4[4] = { xs.x, xs.y, xs.z, xs.w };

    float ot[4];
#pragma unroll
    for (int j = 0; j < 4; ++j)
        ot[j] = (y[j] - mean) * rstd * gwv[j] + gbv[j] + xv4[j];

    *(float4*)(dout + 0 * BH + base + c) = make_float4(ot[0], ot[1], ot[2], ot[3]);
    *(float4*)(dout + 4 * BH + base + c) = make_float4(y[0],  y[1],  y[2],  y[3]);
    *(float4*)(dout + 5 * BH + base + c) = make_float4(cn[0], cn[1], cn[2], cn[3]);
    *(float4*)(dout + 6 * BH + base + c) = make_float4(nn[0], nn[1], nn[2], nn[3]);
    *(float4*)(dout + 7 * BH + base + c) = make_float4(mn[0], mn[1], mn[2], mn[3]);
}

// ---------------- launch -----------------------------------------------------
extern "C" void kernel_launch(void* const* d_in, const int* in_sizes, int n_in,
                              void* d_out, int out_size)
{
    const float* x      = (const float*)d_in[0];
    const float* cs     = (const float*)d_in[1];
    const float* rec    = (const float*)d_in[2];
    const float* cell   = (const float*)d_in[3];
    const float* normst = (const float*)d_in[4];
    const float* maxst  = (const float*)d_in[5];
    const float* ln_w   = (const float*)d_in[6];
    const float* conv_w = (const float*)d_in[7];
    const float* conv_b = (const float*)d_in[8];
    const float* wi_in  = (const float*)d_in[9];
    const float* wf_in  = (const float*)d_in[10];
    const float* wz_in  = (const float*)d_in[11];
    const float* wo_in  = (const float*)d_in[12];
    const float* wi_st  = (const float*)d_in[13];
    const float* wf_st  = (const float*)d_in[14];
    const float* wz_st  = (const float*)d_in[15];
    const float* wo_st  = (const float*)d_in[16];
    const float* bi     = (const float*)d_in[17];
    const float* bf_    = (const float*)d_in[18];
    const float* bz     = (const float*)d_in[19];
    const float* bo     = (const float*)d_in[20];
    const float* gn_w   = (const float*)d_in[21];
    const float* gn_b   = (const float*)d_in[22];
    float* out = (float*)d_out;

    static int smem_set = 0;
    if (!smem_set) {
        cudaFuncSetAttribute(gemm_kernel, cudaFuncAttributeMaxDynamicSharedMemorySize,
                             SMEM_B);
        smem_set = 1;
    }

    ln_conv_kernel<<<BATCH, 256>>>(x, cs, ln_w, conv_w, conv_b,
                                   out + (size_t)BATCH * HDIM);

    convert_w_kernel<<<dim3(4096, 8), 256>>>(wi_in, wf_in, wz_in, wo_in,
                                             wi_st, wf_st, wz_st, wo_st);
    convert_rec_kernel<<<8192, 256>>>(rec);

    dim3 grid(HSZ / BN, BATCH / BM, 16);
    gemm_kernel<<<grid, NTHR, SMEM_B>>>(bi, bf_, bz, bo);

    gate_kernel<<<BATCH * NHEAD, 256>>>(x, cell, normst, maxst, gn_w, gn_b, out);
}

// round 11
// speedup vs baseline: 1.4272x; 1.0252x over previous
#include <cuda_runtime.h>
#include <cuda_bf16.h>
#include <math.h>
#include <stdint.h>

#define BATCH 2048
#define HDIM  4096
#define NHEAD 4
#define HSZ   1024

#define BM 128
#define BN 128
#define BK 32              // fp32 elems per K-chunk (128B data rows)
#define NCHUNK 64          // 2 passes * (1024/32)
#define NTHR 128           // 4 warps, 64x64 per warp

#define TSTRIDE 144        // 128B data + 16B pad; 36 words == 4 mod 32 -> LDSM conflict-free
#define A_TILE_B (128 * TSTRIDE)         // 18432
#define B_TILE_B (128 * TSTRIDE)         // 18432
#define STAGE_B  (A_TILE_B + B_TILE_B)   // 36864
#define SMEM_B   (2 * STAGE_B)           // 73728  (x2 CTAs/SM = 147KB)

#define OFF_A 0
#define OFF_B A_TILE_B

// ---------------- scratch (device globals; no runtime allocation) ----------
__device__ __align__(16) float g_xn   [(size_t)BATCH * HDIM];
__device__ __align__(16) float g_xact [(size_t)BATCH * HDIM];
__device__ __align__(16) float g_rec  [(size_t)BATCH * HDIM];
__device__ __align__(16) float g_w    [8ull * NHEAD * HSZ * HSZ];
__device__ __align__(16) float g_gates[4ull * BATCH * HDIM];

// ---------------- helpers ---------------------------------------------------
__device__ __forceinline__ float warpSum(float v) {
#pragma unroll
    for (int o = 16; o > 0; o >>= 1) v += __shfl_down_sync(0xffffffffu, v, o);
    return v;
}

__device__ __forceinline__ uint32_t smem_u32(const void* p) {
    uint32_t a;
    asm("{ .reg .u64 t; cvta.to.shared.u64 t, %1; cvt.u32.u64 %0, t; }"
        : "=r"(a) : "l"(p));
    return a;
}

__device__ __forceinline__ void cp16(uint32_t saddr, const void* gaddr) {
    asm volatile("cp.async.cg.shared.global [%0], [%1], 16;"
                 :: "r"(saddr), "l"(gaddr));
}

__device__ __forceinline__ float tf32r(float x) {
    uint32_t u;
    asm("cvt.rna.tf32.f32 %0, %1;" : "=r"(u) : "f"(x));
    return __uint_as_float(u);
}

__device__ __forceinline__ void ldsm4(uint32_t* r, uint32_t a) {
    asm volatile("ldmatrix.sync.aligned.m8n8.x4.shared.b16 {%0,%1,%2,%3}, [%4];"
                 : "=r"(r[0]), "=r"(r[1]), "=r"(r[2]), "=r"(r[3]) : "r"(a));
}

__device__ __forceinline__ void mma_tf32(float* c, uint32_t a0, uint32_t a1,
                                         uint32_t a2, uint32_t a3,
                                         uint32_t b0, uint32_t b1) {
    asm volatile(
        "mma.sync.aligned.m16n8k8.row.col.f32.tf32.tf32.f32 "
        "{%0,%1,%2,%3}, {%4,%5,%6,%7}, {%8,%9}, {%0,%1,%2,%3};"
        : "+f"(c[0]), "+f"(c[1]), "+f"(c[2]), "+f"(c[3])
        : "r"(a0), "r"(a1), "r"(a2), "r"(a3), "r"(b0), "r"(b1));
}

// ---------------- Kernel A: layernorm + conv + silu + tf32 emit ------------
__global__ __launch_bounds__(256) void ln_conv_kernel(
    const float* __restrict__ x, const float* __restrict__ cs,
    const float* __restrict__ ln_w, const float* __restrict__ conv_w,
    const float* __restrict__ conv_b, float* __restrict__ out_ncs)
{
    const int b   = blockIdx.x;
    const int tid = threadIdx.x;
    const float* xr = x + (size_t)b * HDIM;

    float4 xv[4];
    float s = 0.f, sq = 0.f;
#pragma unroll
    for (int i = 0; i < 4; i++) {
        xv[i] = *(const float4*)(xr + (size_t)(tid + i * 256) * 4);
        s  += xv[i].x + xv[i].y + xv[i].z + xv[i].w;
        sq += xv[i].x * xv[i].x + xv[i].y * xv[i].y + xv[i].z * xv[i].z + xv[i].w * xv[i].w;
    }
    __shared__ float rs[8], rq[8];
    float ws = warpSum(s), wq = warpSum(sq);
    if ((tid & 31) == 0) { rs[tid >> 5] = ws; rq[tid >> 5] = wq; }
    __syncthreads();
    float ts = 0.f, tq = 0.f;
#pragma unroll
    for (int i = 0; i < 8; i++) { ts += rs[i]; tq += rq[i]; }
    const float mean = ts * (1.f / HDIM);
    const float var  = tq * (1.f / HDIM) - mean * mean;
    const float rstd = rsqrtf(var + 1e-5f);

    const float* csb = cs      + (size_t)b * 3 * HDIM;
    float*       ncs = out_ncs + (size_t)b * 3 * HDIM;

#pragma unroll
    for (int i = 0; i < 4; i++) {
        const int c = (tid + i * 256) * 4;
        float4 lw = *(const float4*)(ln_w + c);
        float4 xn;
        xn.x = (xv[i].x - mean) * rstd * lw.x;
        xn.y = (xv[i].y - mean) * rstd * lw.y;
        xn.z = (xv[i].z - mean) * rstd * lw.z;
        xn.w = (xv[i].w - mean) * rstd * lw.w;

        float4 c0 = *(const float4*)(csb + c);
        float4 c1 = *(const float4*)(csb + HDIM + c);
        float4 c2 = *(const float4*)(csb + 2 * HDIM + c);
        float4 cb = *(const float4*)(conv_b + c);
        float4 w0 = *(const float4*)(conv_w + (size_t)(c + 0) * 4);
        float4 w1 = *(const float4*)(conv_w + (size_t)(c + 1) * 4);
        float4 w2 = *(const float4*)(conv_w + (size_t)(c + 2) * 4);
        float4 w3 = *(const float4*)(conv_w + (size_t)(c + 3) * 4);

        float4 xc;
        xc.x = c0.x * w0.x + c1.x * w0.y + c2.x * w0.z + xn.x * w0.w + cb.x;
        xc.y = c0.y * w1.x + c1.y * w1.y + c2.y * w1.z + xn.y * w1.w + cb.y;
        xc.z = c0.z * w2.x + c1.z * w2.y + c2.z * w2.z + xn.z * w2.w + cb.z;
        xc.w = c0.w * w3.x + c1.w * w3.y + c2.w * w3.z + xn.w * w3.w + cb.w;

        float4 xa;
        xa.x = xc.x / (1.f + expf(-xc.x));
        xa.y = xc.y / (1.f + expf(-xc.y));
        xa.z = xc.z / (1.f + expf(-xc.z));
        xa.w = xc.w / (1.f + expf(-xc.w));

        float4 xnr, xar;
        xnr.x = tf32r(xn.x); xnr.y = tf32r(xn.y); xnr.z = tf32r(xn.z); xnr.w = tf32r(xn.w);
        xar.x = tf32r(xa.x); xar.y = tf32r(xa.y); xar.z = tf32r(xa.z); xar.w = tf32r(xa.w);

        const size_t off = (size_t)b * HDIM + c;
        *(float4*)(g_xn   + off) = xnr;
        *(float4*)(g_xact + off) = xar;

        *(float4*)(ncs + c)            = c1;
        *(float4*)(ncs + HDIM + c)     = c2;
        *(float4*)(ncs + 2 * HDIM + c) = xn;
    }
}

// ---------------- conversion kernels ----------------------------------------
__global__ __launch_bounds__(256) void convert_w_kernel(
    const float* __restrict__ w0, const float* __restrict__ w1,
    const float* __restrict__ w2, const float* __restrict__ w3,
    const float* __restrict__ w4, const float* __restrict__ w5,
    const float* __restrict__ w6, const float* __restrict__ w7)
{
    const float* srcs[8] = { w0, w1, w2, w3, w4, w5, w6, w7 };
    const float* s = srcs[blockIdx.y];
    const size_t base4 = (size_t)blockIdx.y * (NHEAD * HSZ * (HSZ / 4));
    const int i = blockIdx.x * 256 + threadIdx.x;
    float4 v = ((const float4*)s)[i];
    float4 r;
    r.x = tf32r(v.x); r.y = tf32r(v.y); r.z = tf32r(v.z); r.w = tf32r(v.w);
    ((float4*)g_w)[base4 + i] = r;
}

__global__ __launch_bounds__(256) void convert_rec_kernel(const float* __restrict__ src)
{
    const int i = blockIdx.x * 256 + threadIdx.x;
    float4 v = ((const float4*)src)[i];
    float4 r;
    r.x = tf32r(v.x); r.y = tf32r(v.y); r.z = tf32r(v.z); r.w = tf32r(v.w);
    ((float4*)g_rec)[i] = r;
}

// ---------------- Kernel B: TF32 GEMM, 2 CTAs/SM anti-lockstep --------------
__global__ __launch_bounds__(NTHR, 2) void gemm_kernel(
    const float* __restrict__ bi, const float* __restrict__ bf_,
    const float* __restrict__ bz, const float* __restrict__ bo)
{
    extern __shared__ __align__(1024) char smem[];
    const uint32_t sbase = smem_u32(smem);
    const int tid  = threadIdx.x;
    const int wid  = tid >> 5;
    const int lane = tid & 31;

    const int g  = blockIdx.z >> 2;
    const int nh = blockIdx.z & 3;
    const int m0 = blockIdx.y * BM;
    const int n0 = blockIdx.x * BN;

    const float* aSrc0 = (g < 2 ? g_xact : g_xn);
    const size_t wb0 = ((size_t)g)       * NHEAD * HSZ * HSZ + (size_t)nh * HSZ * HSZ;
    const size_t wb1 = ((size_t)(g + 4)) * NHEAD * HSZ * HSZ + (size_t)nh * HSZ * HSZ;

    // loader: 16 cp16 per thread per chunk (A: 8 iters, B: 8 iters)
    auto load_chunk = [&](int c) {
        const int pass = c >> 5;
        const int kt   = (c & 31) * BK;
        const uint32_t st = sbase + (uint32_t)(c & 1) * STAGE_B;
        const float* A = (pass ? g_rec : aSrc0);
        const float* W = g_w + (pass ? wb1 : wb0);
#pragma unroll
        for (int t = 0; t < 8; t++) {
            const int idx = tid + t * NTHR;         // 0..1023
            const int row = idx >> 3;               // 0..127
            const int sec = idx & 7;
            const uint32_t so = (uint32_t)row * TSTRIDE + sec * 16;
            cp16(st + OFF_A + so,
                 A + (size_t)(m0 + row) * HDIM + (size_t)nh * HSZ + kt + sec * 4);
            cp16(st + OFF_B + so,
                 W + (size_t)(n0 + row) * HSZ + kt + sec * 4);
        }
        asm volatile("cp.async.commit_group;");
    };

    // warp tiling: 2 warps along M (64 rows), 2 along N (64 cols)
    const int wm = wid & 1;
    const int wn = wid >> 1;
    const int grp = lane >> 2;      // 0..7
    const int thr = lane & 3;       // 0..3

    // ldmatrix per-lane base addresses (within stage)
    const uint32_t aLdsmBase = OFF_A
        + (uint32_t)(wm * 64 + (lane & 15)) * TSTRIDE
        + (uint32_t)(lane >> 4) * 16;
    const uint32_t bLdsmBase = OFF_B
        + (uint32_t)(wn * 64 + (lane & 7) + (lane >> 4) * 8) * TSTRIDE
        + (uint32_t)((lane >> 3) & 1) * 16;

    float acc[4][8][4];
#pragma unroll
    for (int mi = 0; mi < 4; mi++)
#pragma unroll
        for (int j = 0; j < 8; j++)
#pragma unroll
            for (int q = 0; q < 4; q++) acc[mi][j][q] = 0.f;

    load_chunk(0);

#pragma unroll 1
    for (int c = 0; c < NCHUNK; c++) {
        asm volatile("cp.async.wait_group 0;");   // chunk c landed
        __syncthreads();                          // all warps done computing c-1
        if (c + 1 < NCHUNK) load_chunk(c + 1);    // into other stage, safe now

        const uint32_t st = sbase + (uint32_t)(c & 1) * STAGE_B;
#pragma unroll
        for (int kk = 0; kk < 4; kk++) {          // 4 k-steps of 8
            const uint32_t ka = st + aLdsmBase + kk * 32;
            const uint32_t kb = st + bLdsmBase + kk * 32;

            uint32_t af[4][4];                    // [mi][a0..a3]
#pragma unroll
            for (int mi = 0; mi < 4; mi++)
                ldsm4(af[mi], ka + (uint32_t)(mi * 16) * TSTRIDE);

            uint32_t bf[4][4];                    // [jp][b0,b1,b0',b1']
#pragma unroll
            for (int jp = 0; jp < 4; jp++)
                ldsm4(bf[jp], kb + (uint32_t)(jp * 16) * TSTRIDE);

#pragma unroll
            for (int jp = 0; jp < 4; jp++)
#pragma unroll
                for (int mi = 0; mi < 4; mi++) {
                    mma_tf32(acc[mi][2 * jp],     af[mi][0], af[mi][1], af[mi][2], af[mi][3],
                             bf[jp][0], bf[jp][1]);
                    mma_tf32(acc[mi][2 * jp + 1], af[mi][0], af[mi][1], af[mi][2], af[mi][3],
                             bf[jp][2], bf[jp][3]);
                }
        }
    }

    // epilogue: add bias, write gates
    const float* bias = (g == 0) ? bi : (g == 1) ? bf_ : (g == 2) ? bz : bo;
    float* gbase = g_gates + (size_t)g * BATCH * HDIM;

#pragma unroll
    for (int mi = 0; mi < 4; mi++) {
        const int row0 = m0 + wm * 64 + mi * 16 + grp;
#pragma unroll
        for (int j = 0; j < 8; j++) {
            const int col = n0 + wn * 64 + j * 8 + thr * 2;
            const int h   = nh * HSZ + col;
            const float b0v = bias[h], b1v = bias[h + 1];
            float* p0 = gbase + (size_t)row0 * HDIM + h;
            float* p1 = p0 + 8 * HDIM;
            *(float2*)p0 = make_float2(acc[mi][j][0] + b0v, acc[mi][j][1] + b1v);
            *(float2*)p1 = make_float2(acc[mi][j][2] + b0v, acc[mi][j][3] + b1v);
        }
    }
}

// ---------------- Kernel C: gate math + group norm + outputs ---------------
__global__ __launch_bounds__(256) void gate_kernel(
    const float* __restrict__ x,      const float* __restrict__ cell,
    const float* __restrict__ normst, const float* __restrict__ maxst,
    const float* __restrict__ gn_w,   const float* __restrict__ gn_b,
    float* __restrict__ dout)
{
    const int blk = blockIdx.x;
    const int b = blk >> 2, n = blk & 3;
    const int tid = threadIdx.x;
    const size_t BH = (size_t)BATCH * HDIM;
    const size_t base = (size_t)b * HDIM + n * HSZ;
    const int c = tid * 4;

    float4 t;
    float iv[4], fv[4], zv[4], ov[4], cv[4], nv[4], mv[4];
    t = *(const float4*)(g_gates + 0 * BH + base + c); iv[0]=t.x; iv[1]=t.y; iv[2]=t.z; iv[3]=t.w;
    t = *(const float4*)(g_gates + 1 * BH + base + c); fv[0]=t.x; fv[1]=t.y; fv[2]=t.z; fv[3]=t.w;
    t = *(const float4*)(g_gates + 2 * BH + base + c); zv[0]=t.x; zv[1]=t.y; zv[2]=t.z; zv[3]=t.w;
    t = *(const float4*)(g_gates + 3 * BH + base + c); ov[0]=t.x; ov[1]=t.y; ov[2]=t.z; ov[3]=t.w;
    t = *(const float4*)(cell   + base + c); cv[0]=t.x; cv[1]=t.y; cv[2]=t.z; cv[3]=t.w;
    t = *(const float4*)(normst + base + c); nv[0]=t.x; nv[1]=t.y; nv[2]=t.z; nv[3]=t.w;
    t = *(const float4*)(maxst  + base + c); mv[0]=t.x; mv[1]=t.y; mv[2]=t.z; mv[3]=t.w;

    float y[4], cn[4], nn[4], mn[4];
    float s = 0.f, sq = 0.f;
#pragma unroll
    for (int j = 0; j < 4; ++j) {
        float fj  = fv[j];
        float lsf = fminf(fj, 0.f) - log1pf(expf(-fabsf(fj)));
        float lfm = mv[j] + lsf;
        float ij  = iv[j];
        float mnew = fmaxf(ij, lfm);
        float ig = expf(ij  - mnew);
        float fg = expf(lfm - mnew);
        float cnew = fg * cv[j] + ig * tanhf(zv[j]);
        float nnew = fg * nv[j] + ig;
        float so   = 1.f / (1.f + expf(-ov[j]));
        float yj   = so * cnew / (nnew + 1e-6f);
        y[j] = yj; cn[j] = cnew; nn[j] = nnew; mn[j] = mnew;
        s += yj; sq += yj * yj;
    }

    __shared__ float rs[8], rq[8];
    float ws = warpSum(s), wq = warpSum(sq);
    if ((tid & 31) == 0) { rs[tid >> 5] = ws; rq[tid >> 5] = wq; }
    __syncthreads();
    float ts = 0.f, tq = 0.f;
#pragma unroll
    for (int i = 0; i < 8; i++) { ts += rs[i]; tq += rq[i]; }
    const float mean = ts * (1.f / HSZ);
    const float var  = tq * (1.f / HSZ) - mean * mean;
    const float rstd = rsqrtf(var + 1e-5f);

    const int h = n * HSZ + c;
    float4 gw = *(const float4*)(gn_w + h);
    float4 gb = *(const float4*)(gn_b + h);
    float4 xs = *(const float4*)(x + base + c);
    const float gwv[4] = { gw.x, gw.y, gw.z, gw.w };
    const float gbv[4] = { gb.x, gb.y, gb.z, gb.w };
    const float xv4[4] = { xs.x, xs.y, xs.z, xs.w };

    float ot[4];
#pragma unroll
    for (int j = 0; j < 4; ++j)
        ot[j] = (y[j] - mean) * rstd * gwv[j] + gbv[j] + xv4[j];

    *(float4*)(dout + 0 * BH + base + c) = make_float4(ot[0], ot[1], ot[2], ot[3]);
    *(float4*)(dout + 4 * BH + base + c) = make_float4(y[0],  y[1],  y[2],  y[3]);
    *(float4*)(dout + 5 * BH + base + c) = make_float4(cn[0], cn[1], cn[2], cn[3]);
    *(float4*)(dout + 6 * BH + base + c) = make_float4(nn[0], nn[1], nn[2], nn[3]);
    *(float4*)(dout + 7 * BH + base + c) = make_float4(mn[0], mn[1], mn[2], mn[3]);
}

// ---------------- launch -----------------------------------------------------
extern "C" void kernel_launch(void* const* d_in, const int* in_sizes, int n_in,
                              void* d_out, int out_size)
{
    const float* x      = (const float*)d_in[0];
    const float* cs     = (const float*)d_in[1];
    const float* rec    = (const float*)d_in[2];
    const float* cell   = (const float*)d_in[3];
    const float* normst = (const float*)d_in[4];
    const float* maxst  = (const float*)d_in[5];
    const float* ln_w   = (const float*)d_in[6];
    const float* conv_w = (const float*)d_in[7];
    const float* conv_b = (const float*)d_in[8];
    const float* wi_in  = (const float*)d_in[9];
    const float* wf_in  = (const float*)d_in[10];
    const float* wz_in  = (const float*)d_in[11];
    const float* wo_in  = (const float*)d_in[12];
    const float* wi_st  = (const float*)d_in[13];
    const float* wf_st  = (const float*)d_in[14];
    const float* wz_st  = (const float*)d_in[15];
    const float* wo_st  = (const float*)d_in[16];
    const float* bi     = (const float*)d_in[17];
    const float* bf_    = (const float*)d_in[18];
    const float* bz     = (const float*)d_in[19];
    const float* bo     = (const float*)d_in[20];
    const float* gn_w   = (const float*)d_in[21];
    const float* gn_b   = (const float*)d_in[22];
    float* out = (float*)d_out;

    static int smem_set = 0;
    if (!smem_set) {
        cudaFuncSetAttribute(gemm_kernel, cudaFuncAttributeMaxDynamicSharedMemorySize,
                             SMEM_B);
        smem_set = 1;
    }

    ln_conv_kernel<<<BATCH, 256>>>(x, cs, ln_w, conv_w, conv_b,
                                   out + (size_t)BATCH * HDIM);

    convert_w_kernel<<<dim3(4096, 8), 256>>>(wi_in, wf_in, wz_in, wo_in,
                                             wi_st, wf_st, wz_st, wo_st);
    convert_rec_kernel<<<8192, 256>>>(rec);

    dim3 grid(HSZ / BN, BATCH / BM, 16);
    gemm_kernel<<<grid, NTHR, SMEM_B>>>(bi, bf_, bz, bo);

    gate_kernel<<<BATCH * NHEAD, 256>>>(x, cell, normst, maxst, gn_w, gn_b, out);
}

// round 12
// speedup vs baseline: 1.4364x; 1.0064x over previous
#include <cuda_runtime.h>
#include <cuda_bf16.h>
#include <math.h>
#include <stdint.h>

#define BATCH 2048
#define HDIM  4096
#define NHEAD 4
#define HSZ   1024

#define BM 128
#define BN 128
#define BK 32              // fp32 elems per K-chunk (128B data rows)
#define NCHUNK 64          // 2 passes * (1024/32)
#define NTHR 128           // 4 warps, 64x64 per warp

#define TSTRIDE 144        // 128B data + 16B pad; LDSM conflict-free
#define A_TILE_B (128 * TSTRIDE)         // 18432
#define B_TILE_B (128 * TSTRIDE)         // 18432
#define STAGE_B  (A_TILE_B + B_TILE_B)   // 36864
#define SMEM_B   (2 * STAGE_B)           // 73728  (x2 CTAs/SM = 147KB)

#define OFF_A 0
#define OFF_B A_TILE_B

// ---------------- scratch (device globals; no runtime allocation) ----------
__device__ __align__(16) float g_xn   [(size_t)BATCH * HDIM];
__device__ __align__(16) float g_xact [(size_t)BATCH * HDIM];
__device__ __align__(16) float g_gates[4ull * BATCH * HDIM];

// ---------------- helpers ---------------------------------------------------
__device__ __forceinline__ float warpSum(float v) {
#pragma unroll
    for (int o = 16; o > 0; o >>= 1) v += __shfl_down_sync(0xffffffffu, v, o);
    return v;
}

__device__ __forceinline__ uint32_t smem_u32(const void* p) {
    uint32_t a;
    asm("{ .reg .u64 t; cvta.to.shared.u64 t, %1; cvt.u32.u64 %0, t; }"
        : "=r"(a) : "l"(p));
    return a;
}

__device__ __forceinline__ void cp16(uint32_t saddr, const void* gaddr) {
    asm volatile("cp.async.cg.shared.global [%0], [%1], 16;"
                 :: "r"(saddr), "l"(gaddr));
}

__device__ __forceinline__ float tf32r(float x) {
    uint32_t u;
    asm("cvt.rna.tf32.f32 %0, %1;" : "=r"(u) : "f"(x));
    return __uint_as_float(u);
}

__device__ __forceinline__ void tf32r4(uint32_t* r) {
#pragma unroll
    for (int i = 0; i < 4; i++)
        asm("cvt.rna.tf32.f32 %0, %1;" : "=r"(r[i]) : "f"(__uint_as_float(r[i])));
}

__device__ __forceinline__ void ldsm4(uint32_t* r, uint32_t a) {
    asm volatile("ldmatrix.sync.aligned.m8n8.x4.shared.b16 {%0,%1,%2,%3}, [%4];"
                 : "=r"(r[0]), "=r"(r[1]), "=r"(r[2]), "=r"(r[3]) : "r"(a));
}

__device__ __forceinline__ void mma_tf32(float* c, uint32_t a0, uint32_t a1,
                                         uint32_t a2, uint32_t a3,
                                         uint32_t b0, uint32_t b1) {
    asm volatile(
        "mma.sync.aligned.m16n8k8.row.col.f32.tf32.tf32.f32 "
        "{%0,%1,%2,%3}, {%4,%5,%6,%7}, {%8,%9}, {%0,%1,%2,%3};"
        : "+f"(c[0]), "+f"(c[1]), "+f"(c[2]), "+f"(c[3])
        : "r"(a0), "r"(a1), "r"(a2), "r"(a3), "r"(b0), "r"(b1));
}

// ---------------- Kernel A: layernorm + conv + silu + tf32 emit ------------
__global__ __launch_bounds__(256) void ln_conv_kernel(
    const float* __restrict__ x, const float* __restrict__ cs,
    const float* __restrict__ ln_w, const float* __restrict__ conv_w,
    const float* __restrict__ conv_b, float* __restrict__ out_ncs)
{
    const int b   = blockIdx.x;
    const int tid = threadIdx.x;
    const float* xr = x + (size_t)b * HDIM;

    float4 xv[4];
    float s = 0.f, sq = 0.f;
#pragma unroll
    for (int i = 0; i < 4; i++) {
        xv[i] = *(const float4*)(xr + (size_t)(tid + i * 256) * 4);
        s  += xv[i].x + xv[i].y + xv[i].z + xv[i].w;
        sq += xv[i].x * xv[i].x + xv[i].y * xv[i].y + xv[i].z * xv[i].z + xv[i].w * xv[i].w;
    }
    __shared__ float rs[8], rq[8];
    float ws = warpSum(s), wq = warpSum(sq);
    if ((tid & 31) == 0) { rs[tid >> 5] = ws; rq[tid >> 5] = wq; }
    __syncthreads();
    float ts = 0.f, tq = 0.f;
#pragma unroll
    for (int i = 0; i < 8; i++) { ts += rs[i]; tq += rq[i]; }
    const float mean = ts * (1.f / HDIM);
    const float var  = tq * (1.f / HDIM) - mean * mean;
    const float rstd = rsqrtf(var + 1e-5f);

    const float* csb = cs      + (size_t)b * 3 * HDIM;
    float*       ncs = out_ncs + (size_t)b * 3 * HDIM;

#pragma unroll
    for (int i = 0; i < 4; i++) {
        const int c = (tid + i * 256) * 4;
        float4 lw = *(const float4*)(ln_w + c);
        float4 xn;
        xn.x = (xv[i].x - mean) * rstd * lw.x;
        xn.y = (xv[i].y - mean) * rstd * lw.y;
        xn.z = (xv[i].z - mean) * rstd * lw.z;
        xn.w = (xv[i].w - mean) * rstd * lw.w;

        float4 c0 = *(const float4*)(csb + c);
        float4 c1 = *(const float4*)(csb + HDIM + c);
        float4 c2 = *(const float4*)(csb + 2 * HDIM + c);
        float4 cb = *(const float4*)(conv_b + c);
        float4 w0 = *(const float4*)(conv_w + (size_t)(c + 0) * 4);
        float4 w1 = *(const float4*)(conv_w + (size_t)(c + 1) * 4);
        float4 w2 = *(const float4*)(conv_w + (size_t)(c + 2) * 4);
        float4 w3 = *(const float4*)(conv_w + (size_t)(c + 3) * 4);

        float4 xc;
        xc.x = c0.x * w0.x + c1.x * w0.y + c2.x * w0.z + xn.x * w0.w + cb.x;
        xc.y = c0.y * w1.x + c1.y * w1.y + c2.y * w1.z + xn.y * w1.w + cb.y;
        xc.z = c0.z * w2.x + c1.z * w2.y + c2.z * w2.z + xn.z * w2.w + cb.z;
        xc.w = c0.w * w3.x + c1.w * w3.y + c2.w * w3.z + xn.w * w3.w + cb.w;

        float4 xa;
        xa.x = xc.x / (1.f + expf(-xc.x));
        xa.y = xc.y / (1.f + expf(-xc.y));
        xa.z = xc.z / (1.f + expf(-xc.z));
        xa.w = xc.w / (1.f + expf(-xc.w));

        float4 xnr, xar;
        xnr.x = tf32r(xn.x); xnr.y = tf32r(xn.y); xnr.z = tf32r(xn.z); xnr.w = tf32r(xn.w);
        xar.x = tf32r(xa.x); xar.y = tf32r(xa.y); xar.z = tf32r(xa.z); xar.w = tf32r(xa.w);

        const size_t off = (size_t)b * HDIM + c;
        *(float4*)(g_xn   + off) = xnr;
        *(float4*)(g_xact + off) = xar;

        *(float4*)(ncs + c)            = c1;
        *(float4*)(ncs + HDIM + c)     = c2;
        *(float4*)(ncs + 2 * HDIM + c) = xn;
    }
}

// ---------------- Kernel B: TF32 GEMM, direct weight load + in-reg RNA -----
__global__ __launch_bounds__(NTHR, 2) void gemm_kernel(
    const float* __restrict__ rec,
    const float* __restrict__ wi_in, const float* __restrict__ wf_in,
    const float* __restrict__ wz_in, const float* __restrict__ wo_in,
    const float* __restrict__ wi_st, const float* __restrict__ wf_st,
    const float* __restrict__ wz_st, const float* __restrict__ wo_st,
    const float* __restrict__ bi, const float* __restrict__ bf_,
    const float* __restrict__ bz, const float* __restrict__ bo)
{
    extern __shared__ __align__(1024) char smem[];
    const uint32_t sbase = smem_u32(smem);
    const int tid  = threadIdx.x;
    const int wid  = tid >> 5;
    const int lane = tid & 31;

    const int g  = blockIdx.z >> 2;
    const int nh = blockIdx.z & 3;
    const int m0 = blockIdx.y * BM;
    const int n0 = blockIdx.x * BN;

    const float* Win4[4] = { wi_in, wf_in, wz_in, wo_in };
    const float* Wst4[4] = { wi_st, wf_st, wz_st, wo_st };
    const float* aSrc0 = (g < 2 ? g_xact : g_xn);
    const float* W0 = Win4[g] + (size_t)nh * HSZ * HSZ;
    const float* W1 = Wst4[g] + (size_t)nh * HSZ * HSZ;

    // loader: 16 cp16 per thread per chunk (A: 8 iters, B: 8 iters)
    auto load_chunk = [&](int c) {
        const int pass = c >> 5;
        const int kt   = (c & 31) * BK;
        const uint32_t st = sbase + (uint32_t)(c & 1) * STAGE_B;
        const float* A = (pass ? rec : aSrc0);
        const float* W = (pass ? W1 : W0);
#pragma unroll
        for (int t = 0; t < 8; t++) {
            const int idx = tid + t * NTHR;         // 0..1023
            const int row = idx >> 3;               // 0..127
            const int sec = idx & 7;
            const uint32_t so = (uint32_t)row * TSTRIDE + sec * 16;
            cp16(st + OFF_A + so,
                 A + (size_t)(m0 + row) * HDIM + (size_t)nh * HSZ + kt + sec * 4);
            cp16(st + OFF_B + so,
                 W + (size_t)(n0 + row) * HSZ + kt + sec * 4);
        }
        asm volatile("cp.async.commit_group;");
    };

    // warp tiling: 2 warps along M (64 rows), 2 along N (64 cols)
    const int wm = wid & 1;
    const int wn = wid >> 1;
    const int grp = lane >> 2;      // 0..7
    const int thr = lane & 3;       // 0..3

    const uint32_t aLdsmBase = OFF_A
        + (uint32_t)(wm * 64 + (lane & 15)) * TSTRIDE
        + (uint32_t)(lane >> 4) * 16;
    const uint32_t bLdsmBase = OFF_B
        + (uint32_t)(wn * 64 + (lane & 7) + (lane >> 4) * 8) * TSTRIDE
        + (uint32_t)((lane >> 3) & 1) * 16;

    float acc[4][8][4];
#pragma unroll
    for (int mi = 0; mi < 4; mi++)
#pragma unroll
        for (int j = 0; j < 8; j++)
#pragma unroll
            for (int q = 0; q < 4; q++) acc[mi][j][q] = 0.f;

    load_chunk(0);

#pragma unroll 1
    for (int c = 0; c < NCHUNK; c++) {
        asm volatile("cp.async.wait_group 0;");   // chunk c landed
        __syncthreads();                          // all warps done computing c-1
        if (c + 1 < NCHUNK) load_chunk(c + 1);    // into other stage, safe now

        const uint32_t st = sbase + (uint32_t)(c & 1) * STAGE_B;
#pragma unroll
        for (int kk = 0; kk < 4; kk++) {          // 4 k-steps of 8
            const uint32_t ka = st + aLdsmBase + kk * 32;
            const uint32_t kb = st + bLdsmBase + kk * 32;

            uint32_t af[4][4];
#pragma unroll
            for (int mi = 0; mi < 4; mi++) {
                ldsm4(af[mi], ka + (uint32_t)(mi * 16) * TSTRIDE);
                tf32r4(af[mi]);                   // idempotent for pass-0 A
            }
            uint32_t bf[4][4];
#pragma unroll
            for (int jp = 0; jp < 4; jp++) {
                ldsm4(bf[jp], kb + (uint32_t)(jp * 16) * TSTRIDE);
                tf32r4(bf[jp]);                   // RNA-round raw fp32 weights
            }

#pragma unroll
            for (int jp = 0; jp < 4; jp++)
#pragma unroll
                for (int mi = 0; mi < 4; mi++) {
                    mma_tf32(acc[mi][2 * jp],     af[mi][0], af[mi][1], af[mi][2], af[mi][3],
                             bf[jp][0], bf[jp][1]);
                    mma_tf32(acc[mi][2 * jp + 1], af[mi][0], af[mi][1], af[mi][2], af[mi][3],
                             bf[jp][2], bf[jp][3]);
                }
        }
    }

    // epilogue: add bias, write gates
    const float* bias = (g == 0) ? bi : (g == 1) ? bf_ : (g == 2) ? bz : bo;
    float* gbase = g_gates + (size_t)g * BATCH * HDIM;

#pragma unroll
    for (int mi = 0; mi < 4; mi++) {
        const int row0 = m0 + wm * 64 + mi * 16 + grp;
#pragma unroll
        for (int j = 0; j < 8; j++) {
            const int col = n0 + wn * 64 + j * 8 + thr * 2;
            const int h   = nh * HSZ + col;
            const float b0v = bias[h], b1v = bias[h + 1];
            float* p0 = gbase + (size_t)row0 * HDIM + h;
            float* p1 = p0 + 8 * HDIM;
            *(float2*)p0 = make_float2(acc[mi][j][0] + b0v, acc[mi][j][1] + b1v);
            *(float2*)p1 = make_float2(acc[mi][j][2] + b0v, acc[mi][j][3] + b1v);
        }
    }
}

// ---------------- Kernel C: gate math + group norm + outputs ---------------
__global__ __launch_bounds__(256) void gate_kernel(
    const float* __restrict__ x,      const float* __restrict__ cell,
    const float* __restrict__ normst, const float* __restrict__ maxst,
    const float* __restrict__ gn_w,   const float* __restrict__ gn_b,
    float* __restrict__ dout)
{
    const int blk = blockIdx.x;
    const int b = blk >> 2, n = blk & 3;
    const int tid = threadIdx.x;
    const size_t BH = (size_t)BATCH * HDIM;
    const size_t base = (size_t)b * HDIM + n * HSZ;
    const int c = tid * 4;

    float4 t;
    float iv[4], fv[4], zv[4], ov[4], cv[4], nv[4], mv[4];
    t = *(const float4*)(g_gates + 0 * BH + base + c); iv[0]=t.x; iv[1]=t.y; iv[2]=t.z; iv[3]=t.w;
    t = *(const float4*)(g_gates + 1 * BH + base + c); fv[0]=t.x; fv[1]=t.y; fv[2]=t.z; fv[3]=t.w;
    t = *(const float4*)(g_gates + 2 * BH + base + c); zv[0]=t.x; zv[1]=t.y; zv[2]=t.z; zv[3]=t.w;
    t = *(const float4*)(g_gates + 3 * BH + base + c); ov[0]=t.x; ov[1]=t.y; ov[2]=t.z; ov[3]=t.w;
    t = *(const float4*)(cell   + base + c); cv[0]=t.x; cv[1]=t.y; cv[2]=t.z; cv[3]=t.w;
    t = *(const float4*)(normst + base + c); nv[0]=t.x; nv[1]=t.y; nv[2]=t.z; nv[3]=t.w;
    t = *(const float4*)(maxst  + base + c); mv[0]=t.x; mv[1]=t.y; mv[2]=t.z; mv[3]=t.w;

    float y[4], cn[4], nn[4], mn[4];
    float s = 0.f, sq = 0.f;
#pragma unroll
    for (int j = 0; j < 4; ++j) {
        float fj  = fv[j];
        float lsf = fminf(fj, 0.f) - log1pf(expf(-fabsf(fj)));
        float lfm = mv[j] + lsf;
        float ij  = iv[j];
        float mnew = fmaxf(ij, lfm);
        float ig = expf(ij  - mnew);
        float fg = expf(lfm - mnew);
        float cnew = fg * cv[j] + ig * tanhf(zv[j]);
        float nnew = fg * nv[j] + ig;
        float so   = 1.f / (1.f + expf(-ov[j]));
        float yj   = so * cnew / (nnew + 1e-6f);
        y[j] = yj; cn[j] = cnew; nn[j] = nnew; mn[j] = mnew;
        s += yj; sq += yj * yj;
    }

    __shared__ float rs[8], rq[8];
    float ws = warpSum(s), wq = warpSum(sq);
    if ((tid & 31) == 0) { rs[tid >> 5] = ws; rq[tid >> 5] = wq; }
    __syncthreads();
    float ts = 0.f, tq = 0.f;
#pragma unroll
    for (int i = 0; i < 8; i++) { ts += rs[i]; tq += rq[i]; }
    const float mean = ts * (1.f / HSZ);
    const float var  = tq * (1.f / HSZ) - mean * mean;
    const float rstd = rsqrtf(var + 1e-5f);

    const int h = n * HSZ + c;
    float4 gw = *(const float4*)(gn_w + h);
    float4 gb = *(const float4*)(gn_b + h);
    float4 xs = *(const float4*)(x + base + c);
    const float gwv[4] = { gw.x, gw.y, gw.z, gw.w };
    const float gbv[4] = { gb.x, gb.y, gb.z, gb.w };
    const float xv4[4] = { xs.x, xs.y, xs.z, xs.w };

    float ot[4];
#pragma unroll
    for (int j = 0; j < 4; ++j)
        ot[j] = (y[j] - mean) * rstd * gwv[j] + gbv[j] + xv4[j];

    *(float4*)(dout + 0 * BH + base + c) = make_float4(ot[0], ot[1], ot[2], ot[3]);
    *(float4*)(dout + 4 * BH + base + c) = make_float4(y[0],  y[1],  y[2],  y[3]);
    *(float4*)(dout + 5 * BH + base + c) = make_float4(cn[0], cn[1], cn[2], cn[3]);
    *(float4*)(dout + 6 * BH + base + c) = make_float4(nn[0], nn[1], nn[2], nn[3]);
    *(float4*)(dout + 7 * BH + base + c) = make_float4(mn[0], mn[1], mn[2], mn[3]);
}

// ---------------- launch -----------------------------------------------------
extern "C" void kernel_launch(void* const* d_in, const int* in_sizes, int n_in,
                              void* d_out, int out_size)
{
    const float* x      = (const float*)d_in[0];
    const float* cs     = (const float*)d_in[1];
    const float* rec    = (const float*)d_in[2];
    const float* cell   = (const float*)d_in[3];
    const float* normst = (const float*)d_in[4];
    const float* maxst  = (const float*)d_in[5];
    const float* ln_w   = (const float*)d_in[6];
    const float* conv_w = (const float*)d_in[7];
    const float* conv_b = (const float*)d_in[8];
    const float* wi_in  = (const float*)d_in[9];
    const float* wf_in  = (const float*)d_in[10];
    const float* wz_in  = (const float*)d_in[11];
    const float* wo_in  = (const float*)d_in[12];
    const float* wi_st  = (const float*)d_in[13];
    const float* wf_st  = (const float*)d_in[14];
    const float* wz_st  = (const float*)d_in[15];
    const float* wo_st  = (const float*)d_in[16];
    const float* bi     = (const float*)d_in[17];
    const float* bf_    = (const float*)d_in[18];
    const float* bz     = (const float*)d_in[19];
    const float* bo     = (const float*)d_in[20];
    const float* gn_w   = (const float*)d_in[21];
    const float* gn_b   = (const float*)d_in[22];
    float* out = (float*)d_out;

    static int smem_set = 0;
    if (!smem_set) {
        cudaFuncSetAttribute(gemm_kernel, cudaFuncAttributeMaxDynamicSharedMemorySize,
                             SMEM_B);
        smem_set = 1;
    }

    ln_conv_kernel<<<BATCH, 256>>>(x, cs, ln_w, conv_w, conv_b,
                                   out + (size_t)BATCH * HDIM);

    dim3 grid(HSZ / BN, BATCH / BM, 16);
    gemm_kernel<<<grid, NTHR, SMEM_B>>>(rec,
                                        wi_in, wf_in, wz_in, wo_in,
                                        wi_st, wf_st, wz_st, wo_st,
                                        bi, bf_, bz, bo);

    gate_kernel<<<BATCH * NHEAD, 256>>>(x, cell, normst, maxst, gn_w, gn_b, out);
}